// round 6
// baseline (speedup 1.0000x reference)
#include <cuda_runtime.h>
#include <cuda_bf16.h>
#include <math.h>
#include <stdint.h>

#define B_ 8
#define C_ 256
#define H_ 128
#define W_ 128
#define HW_ 16384
#define HEADS_ 8
#define HD_ 32
#define GSEG 4

typedef __nv_bfloat16 bf16;
typedef __nv_bfloat162 bf162;

// ---------------- scratch (device globals; no allocation allowed) ------------
__device__ bf16 g_bufA[B_ * C_ * HW_];           // q_pre
__device__ bf16 g_bufB[B_ * 2 * C_ * HW_];       // kv_pre
__device__ bf16 g_q[B_ * C_ * HW_];
__device__ bf16 g_k[B_ * C_ * HW_];
__device__ bf16 g_v[B_ * C_ * HW_];
__device__ bf16 g_pe[B_ * C_ * HW_];             // pemb (WITHOUT hx)
__device__ float g_Wq[C_ * C_];
__device__ float g_Wkv[2 * C_ * C_];
__device__ float g_bq[C_];
__device__ float g_bkv[2 * C_];
__device__ float g_rsq[C_];
__device__ float g_rskv[2 * C_];
__device__ float g_ss[2 * B_ * C_];
__device__ float g_part[B_ * HEADS_ * GSEG * 1024];
__device__ float g_attn[B_ * HEADS_ * 1024];
__device__ float g_M[B_ * C_ * C_];

// ---------------- helpers ------------------------------------------------
__device__ __forceinline__ void mma_tf32(float* c, const unsigned* a, unsigned b0, unsigned b1) {
    asm volatile(
        "mma.sync.aligned.m16n8k8.row.col.f32.tf32.tf32.f32 "
        "{%0,%1,%2,%3}, {%4,%5,%6,%7}, {%8,%9}, {%0,%1,%2,%3};\n"
        : "+f"(c[0]), "+f"(c[1]), "+f"(c[2]), "+f"(c[3])
        : "r"(a[0]), "r"(a[1]), "r"(a[2]), "r"(a[3]), "r"(b0), "r"(b1));
}
__device__ __forceinline__ void mma_bf16(float* c, const unsigned* a, unsigned b0, unsigned b1) {
    asm volatile(
        "mma.sync.aligned.m16n8k16.row.col.f32.bf16.bf16.f32 "
        "{%0,%1,%2,%3}, {%4,%5,%6,%7}, {%8,%9}, {%0,%1,%2,%3};\n"
        : "+f"(c[0]), "+f"(c[1]), "+f"(c[2]), "+f"(c[3])
        : "r"(a[0]), "r"(a[1]), "r"(a[2]), "r"(a[3]), "r"(b0), "r"(b1));
}
__device__ __forceinline__ uint32_t smem_u32(const void* p) {
    return (uint32_t)__cvta_generic_to_shared(p);
}
__device__ __forceinline__ void cp16(uint32_t dst, const void* src) {
    asm volatile("cp.async.cg.shared.global [%0], [%1], 16;\n" :: "r"(dst), "l"(src));
}
__device__ __forceinline__ void cp_commit() { asm volatile("cp.async.commit_group;\n"); }
template <int N>
__device__ __forceinline__ void cp_wait() { asm volatile("cp.async.wait_group %0;\n" ::"n"(N)); }

__device__ __forceinline__ float gelu_tanh(float s) {
    float x3 = s * s * s;
    return 0.5f * s * (1.f + tanhf(0.7978845608028654f * (s + 0.044715f * x3)));
}
__device__ __forceinline__ void u4_to_f8(uint4 u, float4& lo, float4& hi) {
    bf162 h0 = *reinterpret_cast<bf162*>(&u.x);
    bf162 h1 = *reinterpret_cast<bf162*>(&u.y);
    bf162 h2 = *reinterpret_cast<bf162*>(&u.z);
    bf162 h3 = *reinterpret_cast<bf162*>(&u.w);
    float2 f0 = __bfloat1622float2(h0), f1 = __bfloat1622float2(h1);
    float2 f2 = __bfloat1622float2(h2), f3 = __bfloat1622float2(h3);
    lo = make_float4(f0.x, f0.y, f1.x, f1.y);
    hi = make_float4(f2.x, f2.y, f3.x, f3.y);
}
__device__ __forceinline__ uint4 f8_to_u4(const float* o) {
    bf162 a = __floats2bfloat162_rn(o[0], o[1]);
    bf162 b = __floats2bfloat162_rn(o[2], o[3]);
    bf162 c = __floats2bfloat162_rn(o[4], o[5]);
    bf162 d = __floats2bfloat162_rn(o[6], o[7]);
    uint4 r;
    r.x = *reinterpret_cast<unsigned*>(&a);
    r.y = *reinterpret_cast<unsigned*>(&b);
    r.z = *reinterpret_cast<unsigned*>(&c);
    r.w = *reinterpret_cast<unsigned*>(&d);
    return r;
}

// 8-wide 3-tap over a padded smem row (data at +4; pads zero at 0..3 / 132..135)
__device__ __forceinline__ void stencil8(const float* R, int s, float w0, float w1, float w2,
                                         float* o) {
    float4 m0 = *reinterpret_cast<const float4*>(R + 4 + s);
    float4 m1 = *reinterpret_cast<const float4*>(R + 8 + s);
    float l = R[3 + s], r = R[12 + s];
    o[0] += w0 * l    + w1 * m0.x + w2 * m0.y;
    o[1] += w0 * m0.x + w1 * m0.y + w2 * m0.z;
    o[2] += w0 * m0.y + w1 * m0.z + w2 * m0.w;
    o[3] += w0 * m0.z + w1 * m0.w + w2 * m1.x;
    o[4] += w0 * m0.w + w1 * m1.x + w2 * m1.y;
    o[5] += w0 * m1.x + w1 * m1.y + w2 * m1.z;
    o[6] += w0 * m1.y + w1 * m1.z + w2 * m1.w;
    o[7] += w0 * m1.z + w1 * m1.w + w2 * r;
}

// single-pass fill of N padded rows from bf16 global (row gr = r0+roff+row; OOB -> zeros)
template <int NROWS>
__device__ __forceinline__ void fill_rows(float (*dst)[136], const bf16* src, int r0, int roff,
                                          int tid) {
    float4 z4 = make_float4(0.f, 0.f, 0.f, 0.f);
    for (int i = tid; i < NROWS * 16; i += 256) {
        int row = i >> 4, c8 = (i & 15) * 8;
        int gr = r0 + roff + row;
        float4 lo = z4, hi = z4;
        if (gr >= 0 && gr < H_) {
            uint4 u = *reinterpret_cast<const uint4*>(src + (size_t)gr * W_ + c8);
            u4_to_f8(u, lo, hi);
        }
        *reinterpret_cast<float4*>(&dst[row][4 + c8]) = lo;
        *reinterpret_cast<float4*>(&dst[row][8 + c8]) = hi;
    }
    for (int i = tid; i < NROWS * 2; i += 256) {
        int row = i >> 1;
        *reinterpret_cast<float4*>(&dst[row][(i & 1) ? 132 : 0]) = z4;
    }
}

// ---------------- weight prep: fold LN gamma/beta into conv1x1 ---------------
__global__ void prep_w_kernel(const float* __restrict__ qw, const float* __restrict__ qb,
                              const float* __restrict__ ln1w, const float* __restrict__ ln1b,
                              const float* __restrict__ kvw, const float* __restrict__ kvb,
                              const float* __restrict__ ln2w, const float* __restrict__ ln2b) {
    int r = blockIdx.x;
    int tid = threadIdx.x;
    if (r < 16) g_ss[r * 256 + tid] = 0.f;
    const float *w, *lnw, *lnb;
    float cb;
    float *dW, *dB, *dR;
    if (r < C_) {
        int o = r;
        w = qw + (size_t)o * C_; lnw = ln1w; lnb = ln1b; cb = qb[o];
        dW = g_Wq + (size_t)o * C_; dB = g_bq + o; dR = g_rsq + o;
    } else {
        int o = r - C_;
        w = kvw + (size_t)o * C_; lnw = ln2w; lnb = ln2b; cb = kvb[o];
        dW = g_Wkv + (size_t)o * C_; dB = g_bkv + o; dR = g_rskv + o;
    }
    float wv = w[tid];
    float we = wv * lnw[tid];
    dW[tid] = we;
    __shared__ float sh1[256], sh2[256];
    sh1[tid] = we;
    sh2[tid] = wv * lnb[tid];
    __syncthreads();
    for (int s = 128; s > 0; s >>= 1) {
        if (tid < s) { sh1[tid] += sh1[tid + s]; sh2[tid] += sh2[tid + s]; }
        __syncthreads();
    }
    if (tid == 0) { *dR = sh1[0]; *dB = cb + sh2[0]; }
}

// ========= LN-fused tensor-core GEMM (tf32, cp.async 3-stage, bf16 out) ======
struct GemmArgs {
    const float* X;
    const float* Wg;
    const float* bias;
    const float* rsum;
    bf16* Yh;
    int O;
};

#define ST_FLOATS 8960   // per stage: A 128*36=4608 + B 32*136=4352

__global__ __launch_bounds__(256, 2) void gemm_ln_kernel(GemmArgs ga) {
    extern __shared__ unsigned sm[];
    __shared__ float s_st[4][128];
    int b = blockIdx.z;
    int oBase = blockIdx.x * 128;
    int pBase = blockIdx.y * 128;
    int tid = threadIdx.x;
    int wid = tid >> 5, lane = tid & 31;
    int g = lane >> 2, tig = lane & 3;
    int oW = (wid >> 2) * 64;
    int pW = (wid & 3) * 32;

    const float* Xb = ga.X + (size_t)b * C_ * HW_;
    const float* Wb = ga.Wg;
    uint32_t smA = smem_u32(sm);

    auto load_stage = [&](int st, int k0) {
        uint32_t baseA = smA + st * ST_FLOATS * 4;
        uint32_t baseB = baseA + 4608 * 4;
#pragma unroll
        for (int i = 0; i < 4; i++) {
            int idx = tid + i * 256;
            int o = idx >> 3, kq = idx & 7;
            cp16(baseA + (o * 36 + kq * 4) * 4, Wb + (size_t)(oBase + o) * C_ + k0 + kq * 4);
        }
#pragma unroll
        for (int i = 0; i < 4; i++) {
            int idx = tid + i * 256;
            int k = idx >> 5, pq = idx & 31;
            cp16(baseB + (k * 136 + pq * 4) * 4, Xb + (size_t)(k0 + k) * HW_ + pBase + pq * 4);
        }
        cp_commit();
    };

    float acc[4][4][4] = {};
    float stS = 0.f, stQ = 0.f;
    int pl_stat = tid & 127, kh_stat = tid >> 7;

    load_stage(0, 0);
    load_stage(1, 32);
    for (int kc = 0; kc < 8; kc++) {
        if (kc + 2 < 8) { load_stage((kc + 2) % 3, (kc + 2) * 32); cp_wait<2>(); }
        else if (kc + 1 < 8) cp_wait<1>();
        else cp_wait<0>();
        __syncthreads();
        unsigned* sA = sm + (kc % 3) * ST_FLOATS;
        unsigned* sB = sA + 4608;
#pragma unroll
        for (int kk = 0; kk < 16; kk++) {
            float v = __uint_as_float(sB[(kh_stat * 16 + kk) * 136 + pl_stat]);
            stS += v; stQ += v * v;
        }
#pragma unroll
        for (int s = 0; s < 32; s += 8) {
            unsigned afr[4][4];
#pragma unroll
            for (int mt = 0; mt < 4; mt++) {
                int ro = oW + mt * 16 + g;
                afr[mt][0] = sA[ro * 36 + s + tig];
                afr[mt][1] = sA[(ro + 8) * 36 + s + tig];
                afr[mt][2] = sA[ro * 36 + s + tig + 4];
                afr[mt][3] = sA[(ro + 8) * 36 + s + tig + 4];
            }
#pragma unroll
            for (int nt = 0; nt < 4; nt++) {
                int cp = pW + nt * 8 + g;
                unsigned b0 = sB[(s + tig) * 136 + cp];
                unsigned b1 = sB[(s + tig + 4) * 136 + cp];
#pragma unroll
                for (int mt = 0; mt < 4; mt++)
                    mma_tf32(acc[mt][nt], afr[mt], b0, b1);
            }
        }
        __syncthreads();
    }

    s_st[kh_stat][pl_stat] = stS;
    s_st[2 + kh_stat][pl_stat] = stQ;
    __syncthreads();
    float mu[4][2], iv[4][2];
#pragma unroll
    for (int nt = 0; nt < 4; nt++) {
#pragma unroll
        for (int u = 0; u < 2; u++) {
            int pl = pW + nt * 8 + 2 * tig + u;
            float s0 = s_st[0][pl] + s_st[1][pl];
            float q0 = s_st[2][pl] + s_st[3][pl];
            float m = s0 * (1.f / 256.f);
            float var = q0 * (1.f / 256.f) - m * m;
            mu[nt][u] = m;
            iv[nt][u] = rsqrtf(var + 1e-5f);
        }
    }
#pragma unroll
    for (int mt = 0; mt < 4; mt++) {
        int o0 = oBase + oW + mt * 16 + g;
        int o1 = o0 + 8;
        float rs0 = ga.rsum[o0], b0v = ga.bias[o0];
        float rs1 = ga.rsum[o1], b1v = ga.bias[o1];
#pragma unroll
        for (int nt = 0; nt < 4; nt++) {
            int p = pBase + pW + nt * 8 + 2 * tig;
            bf162 r0 = __floats2bfloat162_rn(
                iv[nt][0] * (acc[mt][nt][0] - mu[nt][0] * rs0) + b0v,
                iv[nt][1] * (acc[mt][nt][1] - mu[nt][1] * rs0) + b0v);
            bf162 r1 = __floats2bfloat162_rn(
                iv[nt][0] * (acc[mt][nt][2] - mu[nt][0] * rs1) + b1v,
                iv[nt][1] * (acc[mt][nt][3] - mu[nt][1] * rs1) + b1v);
            *reinterpret_cast<bf162*>(ga.Yh + ((size_t)b * ga.O + o0) * HW_ + p) = r0;
            *reinterpret_cast<bf162*>(ga.Yh + ((size_t)b * ga.O + o1) * HW_ + p) = r1;
        }
    }
}

// ------------- depthwise 3x3 for q (32-row tile, 8 cols/thread) --------------
__global__ __launch_bounds__(256) void dwq_kernel(const bf16* __restrict__ X,
                                                  const float* __restrict__ w9,
                                                  const float* __restrict__ bias,
                                                  bf16* __restrict__ out,
                                                  float* __restrict__ ssq) {
    __shared__ float si[34][136];
    int b = blockIdx.z, c = blockIdx.y, r0 = blockIdx.x * 32;
    int tid = threadIdx.x;
    const bf16* Xc = X + ((size_t)(b * C_ + c)) * HW_;
    fill_rows<34>(si, Xc, r0, -1, tid);
    float wk[9];
#pragma unroll
    for (int t = 0; t < 9; t++) wk[t] = __ldg(w9 + (size_t)c * 9 + t);
    float bv = __ldg(bias + c);
    __syncthreads();
    bf16* D = out + ((size_t)(b * C_ + c)) * HW_;
    float ss = 0.f;
    int row0 = tid >> 4, s0 = (tid & 15) * 8;
#pragma unroll
    for (int it = 0; it < 2; it++) {
        int row = row0 + it * 16;
        float o[8] = {bv, bv, bv, bv, bv, bv, bv, bv};
#pragma unroll
        for (int dr = 0; dr < 3; dr++)
            stencil8(si[row + dr], s0, wk[dr * 3], wk[dr * 3 + 1], wk[dr * 3 + 2], o);
        *reinterpret_cast<uint4*>(D + (size_t)(r0 + row) * W_ + s0) = f8_to_u4(o);
#pragma unroll
        for (int u = 0; u < 8; u++) ss += o[u] * o[u];
    }
#pragma unroll
    for (int d = 16; d > 0; d >>= 1) ss += __shfl_down_sync(0xffffffffu, ss, d);
    if ((tid & 31) == 0) atomicAdd(&ssq[b * C_ + c], ss);
}

// ---------------- merged kv dwconv + positional branch (16-row tile) ----------
// k -> g_k (+sumsq); v -> g_v; pemb (NO hx) -> g_pe. st1 aliases dead svi.
__global__ __launch_bounds__(256) void kvpe_kernel(const float* __restrict__ kvw9,
                                                   const float* __restrict__ kvb,
                                                   const float* __restrict__ pe1,
                                                   const float* __restrict__ pe2) {
    __shared__ float sbuf[(18 + 22 + 20) * 136];
    float (*ski)[136] = reinterpret_cast<float(*)[136]>(sbuf);             // 18 rows
    float (*svi)[136] = reinterpret_cast<float(*)[136]>(sbuf + 18 * 136);  // 22 rows
    float (*sv)[136]  = reinterpret_cast<float(*)[136]>(sbuf + 40 * 136);  // 20 rows
    float (*st1)[136] = svi;                                               // alias (18 rows)
    int b = blockIdx.z, c = blockIdx.y, r0 = blockIdx.x * 16;
    int tid = threadIdx.x;
    const bf16* Kc = g_bufB + ((size_t)(b * 2 * C_ + c)) * HW_;
    const bf16* Vc = g_bufB + ((size_t)(b * 2 * C_ + C_ + c)) * HW_;
    fill_rows<18>(ski, Kc, r0, -1, tid);
    fill_rows<22>(svi, Vc, r0, -3, tid);
    {   // zero sv pads
        float4 z4 = make_float4(0.f, 0.f, 0.f, 0.f);
        for (int i = tid; i < 20 * 2; i += 256)
            *reinterpret_cast<float4*>(&sv[i >> 1][(i & 1) ? 132 : 0]) = z4;
    }
    float wkk[9], wkv[9], w1[9], w2[9];
#pragma unroll
    for (int t = 0; t < 9; t++) {
        wkk[t] = __ldg(kvw9 + (size_t)c * 9 + t);
        wkv[t] = __ldg(kvw9 + (size_t)(C_ + c) * 9 + t);
        w1[t] = __ldg(pe1 + (size_t)c * 9 + t);
        w2[t] = __ldg(pe2 + (size_t)c * 9 + t);
    }
    float bk = __ldg(kvb + c);
    float bvv = __ldg(kvb + C_ + c);
    __syncthreads();

    int row0 = tid >> 4, s0 = (tid & 15) * 8;

    // ---- k (16 rows, one position set per thread) ----
    bf16* Dk = g_k + ((size_t)(b * C_ + c)) * HW_;
    float ss = 0.f;
    {
        float o[8] = {bk, bk, bk, bk, bk, bk, bk, bk};
#pragma unroll
        for (int dr = 0; dr < 3; dr++)
            stencil8(ski[row0 + dr], s0, wkk[dr * 3], wkk[dr * 3 + 1], wkk[dr * 3 + 2], o);
        *reinterpret_cast<uint4*>(Dk + (size_t)(r0 + row0) * W_ + s0) = f8_to_u4(o);
#pragma unroll
        for (int u = 0; u < 8; u++) ss += o[u] * o[u];
    }
#pragma unroll
    for (int d = 16; d > 0; d >>= 1) ss += __shfl_down_sync(0xffffffffu, ss, d);
    if ((tid & 31) == 0) atomicAdd(&g_ss[B_ * C_ + b * C_ + c], ss);

    // ---- v (20 rows incl. 2-row halo; OOB rows -> zeros in sv) ----
    bf16* Dv = g_v + ((size_t)(b * C_ + c)) * HW_;
    for (int i = tid; i < 20 * 16; i += 256) {
        int row = i >> 4, cc = (i & 15) * 8;
        int gr = r0 - 2 + row;
        float o[8] = {};
        if (gr >= 0 && gr < H_) {
#pragma unroll
            for (int u = 0; u < 8; u++) o[u] = bvv;
#pragma unroll
            for (int dr = 0; dr < 3; dr++)
                stencil8(svi[row + dr], cc, wkv[dr * 3], wkv[dr * 3 + 1], wkv[dr * 3 + 2], o);
        }
        *reinterpret_cast<float4*>(&sv[row][4 + cc]) = make_float4(o[0], o[1], o[2], o[3]);
        *reinterpret_cast<float4*>(&sv[row][8 + cc]) = make_float4(o[4], o[5], o[6], o[7]);
        if (row >= 2 && row < 18)
            *reinterpret_cast<uint4*>(Dv + (size_t)gr * W_ + cc) = f8_to_u4(o);
    }
    __syncthreads();

    // ---- t1 = gelu(dw(v, pe1)) (18 rows incl. halo) -> st1 (aliases svi) ----
    for (int i = tid; i < 18 * 16; i += 256) {
        int row = i >> 4, cc = (i & 15) * 8;
        int gr = r0 - 1 + row;
        float o[8] = {};
        if (gr >= 0 && gr < H_) {
#pragma unroll
            for (int dr = 0; dr < 3; dr++)
                stencil8(sv[row + dr], cc, w1[dr * 3], w1[dr * 3 + 1], w1[dr * 3 + 2], o);
#pragma unroll
            for (int u = 0; u < 8; u++) o[u] = gelu_tanh(o[u]);
        }
        *reinterpret_cast<float4*>(&st1[row][4 + cc]) = make_float4(o[0], o[1], o[2], o[3]);
        *reinterpret_cast<float4*>(&st1[row][8 + cc]) = make_float4(o[4], o[5], o[6], o[7]);
    }
    __syncthreads();

    // ---- pemb = dw(t1, pe2) (16 rows) -> g_pe ----
    bf16* Dp = g_pe + ((size_t)(b * C_ + c)) * HW_;
    {
        float o[8] = {};
#pragma unroll
        for (int dr = 0; dr < 3; dr++)
            stencil8(st1[row0 + dr], s0, w2[dr * 3], w2[dr * 3 + 1], w2[dr * 3 + 2], o);
        *reinterpret_cast<uint4*>(Dp + (size_t)(r0 + row0) * W_ + s0) = f8_to_u4(o);
    }
}

// ---------------- gram via bf16 mma m16n8k16, split-K=4 ----------------------
__global__ __launch_bounds__(256) void gram_mma() {
    __shared__ float sbuf[8192];
    bf16* sqh = reinterpret_cast<bf16*>(sbuf);
    bf16* skh = sqh + 32 * 136;
    unsigned* squ = reinterpret_cast<unsigned*>(sqh);
    unsigned* sku = reinterpret_cast<unsigned*>(skh);
    int seg = blockIdx.x, h = blockIdx.y, b = blockIdx.z;
    const bf16* Q = g_q + ((size_t)(b * C_ + h * HD_)) * HW_;
    const bf16* K = g_k + ((size_t)(b * C_ + h * HD_)) * HW_;
    int tid = threadIdx.x, wid = tid >> 5, lane = tid & 31;
    int g = lane >> 2, tig = lane & 3;
    float acc[2][4][4] = {};
    int n0 = seg * (HW_ / GSEG);
    int klu = wid * 8;
    for (int ch = 0; ch < (HW_ / GSEG) / 128; ch++) {
        int base = n0 + ch * 128;
        for (int i = tid; i < 32 * 16; i += 256) {
            int row = i >> 4, c8 = (i & 15) * 8;
            *reinterpret_cast<uint4*>(sqh + row * 136 + c8) =
                *reinterpret_cast<const uint4*>(Q + (size_t)row * HW_ + base + c8);
            *reinterpret_cast<uint4*>(skh + row * 136 + c8) =
                *reinterpret_cast<const uint4*>(K + (size_t)row * HW_ + base + c8);
        }
        __syncthreads();
        unsigned afr[2][4];
#pragma unroll
        for (int mt = 0; mt < 2; mt++) {
            int r = mt * 16 + g;
            afr[mt][0] = squ[r * 68 + klu + tig];
            afr[mt][1] = squ[(r + 8) * 68 + klu + tig];
            afr[mt][2] = squ[r * 68 + klu + 4 + tig];
            afr[mt][3] = squ[(r + 8) * 68 + klu + 4 + tig];
        }
#pragma unroll
        for (int nt = 0; nt < 4; nt++) {
            unsigned b0 = sku[(nt * 8 + g) * 68 + klu + tig];
            unsigned b1 = sku[(nt * 8 + g) * 68 + klu + 4 + tig];
#pragma unroll
            for (int mt = 0; mt < 2; mt++)
                mma_bf16(acc[mt][nt], afr[mt], b0, b1);
        }
        __syncthreads();
    }
    float* red = sbuf;
#pragma unroll
    for (int mt = 0; mt < 2; mt++)
#pragma unroll
        for (int nt = 0; nt < 4; nt++) {
            int r = mt * 16 + g, cl = nt * 8 + 2 * tig;
            red[wid * 1024 + r * 32 + cl] = acc[mt][nt][0];
            red[wid * 1024 + r * 32 + cl + 1] = acc[mt][nt][1];
            red[wid * 1024 + (r + 8) * 32 + cl] = acc[mt][nt][2];
            red[wid * 1024 + (r + 8) * 32 + cl + 1] = acc[mt][nt][3];
        }
    __syncthreads();
    float* outp = g_part + ((size_t)(b * HEADS_ + h) * GSEG + seg) * 1024;
    for (int i = tid; i < 1024; i += 256) {
        float s = 0.f;
#pragma unroll
        for (int w = 0; w < 8; w++) s += red[w * 1024 + i];
        outp[i] = s;
    }
}

// ---------------- softmax with fused q/k norm scales + temperature -----------
__global__ void softmax_kernel(const float* __restrict__ temp) {
    int bh = blockIdx.x;
    int b = bh >> 3, h = bh & 7;
    int i = threadIdx.x;
    float qs = 1.f / fmaxf(sqrtf(g_ss[b * C_ + h * HD_ + i]), 1e-12f);
    float T = __ldg(temp + h);
    float v[32];
    float mx = -1e30f;
#pragma unroll 4
    for (int j = 0; j < 32; j++) {
        float s = 0.f;
#pragma unroll
        for (int seg = 0; seg < GSEG; seg++)
            s += g_part[((size_t)bh * GSEG + seg) * 1024 + i * 32 + j];
        float ks = 1.f / fmaxf(sqrtf(g_ss[B_ * C_ + b * C_ + h * HD_ + j]), 1e-12f);
        float val = s * qs * ks * T;
        v[j] = val;
        mx = fmaxf(mx, val);
    }
    float sum = 0.f;
#pragma unroll
    for (int j = 0; j < 32; j++) {
        v[j] = expf(v[j] - mx);
        sum += v[j];
    }
    float inv = 1.f / sum;
#pragma unroll
    for (int j = 0; j < 32; j++) g_attn[bh * 1024 + i * 32 + j] = v[j] * inv;
}

// ---------------- M[b] = ao_w @ blockdiag(attn[b]) ---------------------------
__global__ void buildM_kernel(const float* __restrict__ ao_w) {
    int h = blockIdx.x, b = blockIdx.y;
    int tid = threadIdx.x;
    __shared__ float sa[32][33];
#pragma unroll
    for (int t = 0; t < 4; t++) {
        int idx = tid + t * 256;
        sa[idx >> 5][idx & 31] = g_attn[(b * HEADS_ + h) * 1024 + idx];
    }
    __syncthreads();
    float wreg[32];
#pragma unroll
    for (int c = 0; c < 32; c++) wreg[c] = ao_w[(size_t)tid * C_ + h * HD_ + c];
#pragma unroll 4
    for (int d = 0; d < 32; d++) {
        float m = 0.f;
#pragma unroll
        for (int c = 0; c < 32; c++) m += wreg[c] * sa[c][d];
        g_M[((size_t)(b * C_) + tid) * C_ + h * HD_ + d] = m;
    }
}

// ======= final GEMM: out = M[b] @ v + ao_b + pemb + hx (tf32, bf16 B) ========
__global__ __launch_bounds__(256, 2) void gemm_out_kernel(const float* __restrict__ bias,
                                                          const float* __restrict__ hx,
                                                          float* __restrict__ out) {
    extern __shared__ float sm2[];
    int b = blockIdx.z;
    int oBase = blockIdx.x * 128;
    int pBase = blockIdx.y * 128;
    int tid = threadIdx.x;
    int wid = tid >> 5, lane = tid & 31;
    int g = lane >> 2, tig = lane & 3;
    int oW = (wid >> 2) * 64;
    int pW = (wid & 3) * 32;

    const float* Mb = g_M + (size_t)b * C_ * C_;
    const bf16* Vb = g_v + (size_t)b * C_ * HW_;

    float4 aR[4];
    uint4 bR[2];
    auto ldg_stage = [&](int k0) {
#pragma unroll
        for (int i = 0; i < 4; i++) {
            int idx = tid + i * 256;
            int o = idx >> 3, kq = idx & 7;
            aR[i] = *reinterpret_cast<const float4*>(Mb + (size_t)(oBase + o) * C_ + k0 + kq * 4);
        }
#pragma unroll
        for (int i = 0; i < 2; i++) {
            int idx = tid + i * 256;
            int k = idx >> 4, c8 = (idx & 15) * 8;
            bR[i] = *reinterpret_cast<const uint4*>(Vb + (size_t)(k0 + k) * HW_ + pBase + c8);
        }
    };
    auto sts_stage = [&](int st) {
        float* sA = sm2 + st * ST_FLOATS;
        float* sB = sA + 4608;
#pragma unroll
        for (int i = 0; i < 4; i++) {
            int idx = tid + i * 256;
            int o = idx >> 3, kq = idx & 7;
            *reinterpret_cast<float4*>(sA + o * 36 + kq * 4) = aR[i];
        }
#pragma unroll
        for (int i = 0; i < 2; i++) {
            int idx = tid + i * 256;
            int k = idx >> 4, c8 = (idx & 15) * 8;
            float4 lo, hi;
            u4_to_f8(bR[i], lo, hi);
            *reinterpret_cast<float4*>(sB + k * 136 + c8) = lo;
            *reinterpret_cast<float4*>(sB + k * 136 + c8 + 4) = hi;
        }
    };

    float acc[4][4][4] = {};
    ldg_stage(0);
    for (int kc = 0; kc < 8; kc++) {
        sts_stage(kc & 1);
        __syncthreads();
        if (kc < 7) ldg_stage((kc + 1) * 32);
        unsigned* sA = reinterpret_cast<unsigned*>(sm2 + (kc & 1) * ST_FLOATS);
        unsigned* sB = sA + 4608;
#pragma unroll
        for (int s = 0; s < 32; s += 8) {
            unsigned afr[4][4];
#pragma unroll
            for (int mt = 0; mt < 4; mt++) {
                int ro = oW + mt * 16 + g;
                afr[mt][0] = sA[ro * 36 + s + tig];
                afr[mt][1] = sA[(ro + 8) * 36 + s + tig];
                afr[mt][2] = sA[ro * 36 + s + tig + 4];
                afr[mt][3] = sA[(ro + 8) * 36 + s + tig + 4];
            }
#pragma unroll
            for (int nt = 0; nt < 4; nt++) {
                int cp = pW + nt * 8 + g;
                unsigned b0 = sB[(s + tig) * 136 + cp];
                unsigned b1 = sB[(s + tig + 4) * 136 + cp];
#pragma unroll
                for (int mt = 0; mt < 4; mt++)
                    mma_tf32(acc[mt][nt], afr[mt], b0, b1);
            }
        }
        __syncthreads();
    }

    const bf16* PEb = g_pe + (size_t)b * C_ * HW_;
    const float* HXb = hx + (size_t)b * C_ * HW_;
#pragma unroll
    for (int mt = 0; mt < 4; mt++) {
        int o0 = oBase + oW + mt * 16 + g;
        int o1 = o0 + 8;
        float b0v = bias[o0], b1v = bias[o1];
#pragma unroll
        for (int nt = 0; nt < 4; nt++) {
            int p = pBase + pW + nt * 8 + 2 * tig;
            float2 h0 = *reinterpret_cast<const float2*>(HXb + (size_t)o0 * HW_ + p);
            float2 h1 = *reinterpret_cast<const float2*>(HXb + (size_t)o1 * HW_ + p);
            float2 pf0 = __bfloat1622float2(
                *reinterpret_cast<const bf162*>(PEb + (size_t)o0 * HW_ + p));
            float2 pf1 = __bfloat1622float2(
                *reinterpret_cast<const bf162*>(PEb + (size_t)o1 * HW_ + p));
            float2 r0, r1;
            r0.x = acc[mt][nt][0] + b0v + pf0.x + h0.x;
            r0.y = acc[mt][nt][1] + b0v + pf0.y + h0.y;
            r1.x = acc[mt][nt][2] + b1v + pf1.x + h1.x;
            r1.y = acc[mt][nt][3] + b1v + pf1.y + h1.y;
            *reinterpret_cast<float2*>(out + ((size_t)b * C_ + o0) * HW_ + p) = r0;
            *reinterpret_cast<float2*>(out + ((size_t)b * C_ + o1) * HW_ + p) = r1;
        }
    }
}

// -----------------------------------------------------------------------------
extern "C" void kernel_launch(void* const* d_in, const int* in_sizes, int n_in,
                              void* d_out, int out_size) {
    const float* x = (const float*)d_in[0];
    const float* hx = (const float*)d_in[1];
    const float* ln1_w = (const float*)d_in[2];
    const float* ln1_b = (const float*)d_in[3];
    const float* ln2_w = (const float*)d_in[4];
    const float* ln2_b = (const float*)d_in[5];
    const float* q_w = (const float*)d_in[6];
    const float* q_b = (const float*)d_in[7];
    const float* q_dw_w = (const float*)d_in[8];
    const float* q_dw_b = (const float*)d_in[9];
    const float* kv_w = (const float*)d_in[10];
    const float* kv_b = (const float*)d_in[11];
    const float* kv_dw_w = (const float*)d_in[12];
    const float* kv_dw_b = (const float*)d_in[13];
    const float* ao_w = (const float*)d_in[14];
    const float* ao_b = (const float*)d_in[15];
    const float* pe1_w = (const float*)d_in[16];
    const float* pe2_w = (const float*)d_in[17];
    const float* temperature = (const float*)d_in[18];
    float* out = (float*)d_out;

    // fork-join resources, created once OUTSIDE graph capture (correctness call
    // precedes capture). Same launch structure on every call — deterministic.
    static cudaStream_t s_aux = nullptr;
    static cudaEvent_t e_fork = nullptr, e_join = nullptr;
    if (s_aux == nullptr) {
        cudaStreamCreateWithFlags(&s_aux, cudaStreamNonBlocking);
        cudaEventCreateWithFlags(&e_fork, cudaEventDisableTiming);
        cudaEventCreateWithFlags(&e_join, cudaEventDisableTiming);
    }

    float *p_Wq, *p_Wkv, *p_bq, *p_bkv, *p_rsq, *p_rskv, *p_ss;
    bf16 *p_bufA, *p_bufB, *p_q;
    cudaGetSymbolAddress((void**)&p_Wq, g_Wq);
    cudaGetSymbolAddress((void**)&p_Wkv, g_Wkv);
    cudaGetSymbolAddress((void**)&p_bq, g_bq);
    cudaGetSymbolAddress((void**)&p_bkv, g_bkv);
    cudaGetSymbolAddress((void**)&p_rsq, g_rsq);
    cudaGetSymbolAddress((void**)&p_rskv, g_rskv);
    cudaGetSymbolAddress((void**)&p_ss, g_ss);
    cudaGetSymbolAddress((void**)&p_bufA, g_bufA);
    cudaGetSymbolAddress((void**)&p_bufB, g_bufB);
    cudaGetSymbolAddress((void**)&p_q, g_q);

    const int gemm_smem = 3 * ST_FLOATS * 4;     // 107520 B
    const int out_smem = 2 * ST_FLOATS * 4;      // 71680 B
    cudaFuncSetAttribute(gemm_ln_kernel, cudaFuncAttributeMaxDynamicSharedMemorySize, gemm_smem);
    cudaFuncSetAttribute(gemm_out_kernel, cudaFuncAttributeMaxDynamicSharedMemorySize, out_smem);

    // 1. fold LN into weights; zero sumsq accumulators (stream 0, pre-fork)
    prep_w_kernel<<<3 * C_, 256>>>(q_w, q_b, ln1_w, ln1_b, kv_w, kv_b, ln2_w, ln2_b);

    // fork: q chain on s_aux, kv chain on stream 0
    cudaEventRecord(e_fork, 0);
    cudaStreamWaitEvent(s_aux, e_fork, 0);

    // --- q chain (aux stream) ---
    {
        GemmArgs ga{};
        ga.X = x; ga.Wg = p_Wq; ga.bias = p_bq; ga.rsum = p_rsq;
        ga.Yh = p_bufA; ga.O = C_;
        gemm_ln_kernel<<<dim3(C_ / 128, HW_ / 128, B_), 256, gemm_smem, s_aux>>>(ga);
    }
    dwq_kernel<<<dim3(4, C_, B_), 256, 0, s_aux>>>(p_bufA, q_dw_w, q_dw_b, p_q, p_ss);
    cudaEventRecord(e_join, s_aux);

    // --- kv chain (stream 0) ---
    {
        GemmArgs ga{};
        ga.X = hx; ga.Wg = p_Wkv; ga.bias = p_bkv; ga.rsum = p_rskv;
        ga.Yh = p_bufB; ga.O = 2 * C_;
        gemm_ln_kernel<<<dim3(2 * C_ / 128, HW_ / 128, B_), 256, gemm_smem>>>(ga);
    }
    kvpe_kernel<<<dim3(8, C_, B_), 256>>>(kv_dw_w, kv_dw_b, pe1_w, pe2_w);

    // join
    cudaStreamWaitEvent(0, e_join, 0);

    // 5. gram (bf16 mma, split-K=4), softmax with fused norms
    gram_mma<<<dim3(GSEG, HEADS_, B_), 256>>>();
    softmax_kernel<<<B_ * HEADS_, 32>>>(temperature);

    // 6. fold attn into output projection; final fused GEMM
    buildM_kernel<<<dim3(HEADS_, B_), 256>>>(ao_w);
    gemm_out_kernel<<<dim3(C_ / 128, HW_ / 128, B_), 256, out_smem>>>(ao_b, hx, out);
}

// round 7
// speedup vs baseline: 1.1206x; 1.1206x over previous
#include <cuda_runtime.h>
#include <cuda_bf16.h>
#include <math.h>
#include <stdint.h>

#define B_ 8
#define C_ 256
#define H_ 128
#define W_ 128
#define HW_ 16384
#define HEADS_ 8
#define HD_ 32
#define GSEG 4

typedef __nv_bfloat16 bf16;
typedef __nv_bfloat162 bf162;

// ---------------- scratch (device globals; no allocation allowed) ------------
__device__ bf16 g_bufA[B_ * C_ * HW_];           // q_pre
__device__ bf16 g_bufB[B_ * 2 * C_ * HW_];       // kv_pre
__device__ bf16 g_q[B_ * C_ * HW_];
__device__ bf16 g_k[B_ * C_ * HW_];
__device__ bf16 g_v[B_ * C_ * HW_];
__device__ bf16 g_pe[B_ * C_ * HW_];             // pemb (WITHOUT hx)
__device__ unsigned g_Wqh[C_ * 128];             // bf16-pair packed folded weights
__device__ unsigned g_Wkvh[2 * C_ * 128];
__device__ unsigned g_Mh[B_ * C_ * 128];         // packed M = ao_w @ blockdiag(attn)
__device__ float g_bq[C_];
__device__ float g_bkv[2 * C_];
__device__ float g_rsq[C_];
__device__ float g_rskv[2 * C_];
__device__ float g_ss[2 * B_ * C_];
__device__ float g_part[B_ * HEADS_ * GSEG * 1024];
__device__ float g_attn[B_ * HEADS_ * 1024];

// ---------------- helpers ------------------------------------------------
__device__ __forceinline__ void mma_bf16(float* c, const unsigned* a, unsigned b0, unsigned b1) {
    asm volatile(
        "mma.sync.aligned.m16n8k16.row.col.f32.bf16.bf16.f32 "
        "{%0,%1,%2,%3}, {%4,%5,%6,%7}, {%8,%9}, {%0,%1,%2,%3};\n"
        : "+f"(c[0]), "+f"(c[1]), "+f"(c[2]), "+f"(c[3])
        : "r"(a[0]), "r"(a[1]), "r"(a[2]), "r"(a[3]), "r"(b0), "r"(b1));
}
__device__ __forceinline__ unsigned packbf(float lo, float hi) {
    bf162 t = __floats2bfloat162_rn(lo, hi);
    return *reinterpret_cast<unsigned*>(&t);
}
__device__ __forceinline__ float gelu_tanh(float s) {
    float x3 = s * s * s;
    return 0.5f * s * (1.f + tanhf(0.7978845608028654f * (s + 0.044715f * x3)));
}
__device__ __forceinline__ void u4_to_f8(uint4 u, float4& lo, float4& hi) {
    bf162 h0 = *reinterpret_cast<bf162*>(&u.x);
    bf162 h1 = *reinterpret_cast<bf162*>(&u.y);
    bf162 h2 = *reinterpret_cast<bf162*>(&u.z);
    bf162 h3 = *reinterpret_cast<bf162*>(&u.w);
    float2 f0 = __bfloat1622float2(h0), f1 = __bfloat1622float2(h1);
    float2 f2 = __bfloat1622float2(h2), f3 = __bfloat1622float2(h3);
    lo = make_float4(f0.x, f0.y, f1.x, f1.y);
    hi = make_float4(f2.x, f2.y, f3.x, f3.y);
}
__device__ __forceinline__ uint4 f8_to_u4(const float* o) {
    uint4 r;
    r.x = packbf(o[0], o[1]);
    r.y = packbf(o[2], o[3]);
    r.z = packbf(o[4], o[5]);
    r.w = packbf(o[6], o[7]);
    return r;
}

// 8-wide 3-tap over a padded smem row (data at +4; pads zero at 0..3 / 132..135)
__device__ __forceinline__ void stencil8(const float* R, int s, float w0, float w1, float w2,
                                         float* o) {
    float4 m0 = *reinterpret_cast<const float4*>(R + 4 + s);
    float4 m1 = *reinterpret_cast<const float4*>(R + 8 + s);
    float l = R[3 + s], r = R[12 + s];
    o[0] += w0 * l    + w1 * m0.x + w2 * m0.y;
    o[1] += w0 * m0.x + w1 * m0.y + w2 * m0.z;
    o[2] += w0 * m0.y + w1 * m0.z + w2 * m0.w;
    o[3] += w0 * m0.z + w1 * m0.w + w2 * m1.x;
    o[4] += w0 * m0.w + w1 * m1.x + w2 * m1.y;
    o[5] += w0 * m1.x + w1 * m1.y + w2 * m1.z;
    o[6] += w0 * m1.y + w1 * m1.z + w2 * m1.w;
    o[7] += w0 * m1.z + w1 * m1.w + w2 * r;
}

// single-pass fill of N padded rows from bf16 global (row gr = r0+roff+row; OOB -> zeros)
template <int NROWS>
__device__ __forceinline__ void fill_rows(float (*dst)[136], const bf16* src, int r0, int roff,
                                          int tid) {
    float4 z4 = make_float4(0.f, 0.f, 0.f, 0.f);
    for (int i = tid; i < NROWS * 16; i += 256) {
        int row = i >> 4, c8 = (i & 15) * 8;
        int gr = r0 + roff + row;
        float4 lo = z4, hi = z4;
        if (gr >= 0 && gr < H_) {
            uint4 u = *reinterpret_cast<const uint4*>(src + (size_t)gr * W_ + c8);
            u4_to_f8(u, lo, hi);
        }
        *reinterpret_cast<float4*>(&dst[row][4 + c8]) = lo;
        *reinterpret_cast<float4*>(&dst[row][8 + c8]) = hi;
    }
    for (int i = tid; i < NROWS * 2; i += 256) {
        int row = i >> 1;
        *reinterpret_cast<float4*>(&dst[row][(i & 1) ? 132 : 0]) = z4;
    }
}

// ---------------- weight prep: fold LN gamma/beta, pack to bf16 pairs --------
__global__ void prep_w_kernel(const float* __restrict__ qw, const float* __restrict__ qb,
                              const float* __restrict__ ln1w, const float* __restrict__ ln1b,
                              const float* __restrict__ kvw, const float* __restrict__ kvb,
                              const float* __restrict__ ln2w, const float* __restrict__ ln2b) {
    int r = blockIdx.x;
    int tid = threadIdx.x;
    if (r < 16) g_ss[r * 256 + tid] = 0.f;
    const float *w, *lnw, *lnb;
    float cb;
    unsigned* dWh;
    float *dB, *dR;
    if (r < C_) {
        int o = r;
        w = qw + (size_t)o * C_; lnw = ln1w; lnb = ln1b; cb = qb[o];
        dWh = g_Wqh + (size_t)o * 128; dB = g_bq + o; dR = g_rsq + o;
    } else {
        int o = r - C_;
        w = kvw + (size_t)o * C_; lnw = ln2w; lnb = ln2b; cb = kvb[o];
        dWh = g_Wkvh + (size_t)o * 128; dB = g_bkv + o; dR = g_rskv + o;
    }
    float wv = w[tid];
    float we = wv * lnw[tid];
    // round to bf16 once; use rounded value for BOTH the packed weight and rsum
    float we_r = __bfloat162float(__float2bfloat16(we));
    __shared__ float shw[256], sh1[256], sh2[256];
    shw[tid] = we_r;
    sh1[tid] = we_r;
    sh2[tid] = wv * lnb[tid];
    __syncthreads();
    if (tid < 128) dWh[tid] = packbf(shw[2 * tid], shw[2 * tid + 1]);
    for (int s = 128; s > 0; s >>= 1) {
        if (tid < s) { sh1[tid] += sh1[tid + s]; sh2[tid] += sh2[tid + s]; }
        __syncthreads();
    }
    if (tid == 0) { *dR = sh1[0]; *dB = cb + sh2[0]; }
}

// ========= LN-fused GEMM: bf16 m16n8k16, fp32 X -> bf16 pack on the fly ======
// A: packed weights [o][k2] uints.  B: X fp32 [k][p] global, packed to sB [k2][p].
// Stats accumulated from fp32 registers (exact), reduced in smem.
struct GemmArgs {
    const float* X;
    const unsigned* Wh;
    const float* bias;
    const float* rsum;
    bf16* Yh;
    int O;
};

#define SA_U 20
#define SB_U 136
#define STG_U (128 * SA_U + 16 * SB_U)   // 4736 uints / stage

__global__ __launch_bounds__(256, 2) void gemm_lnh_kernel(GemmArgs ga) {
    __shared__ unsigned sm[2 * STG_U];
    __shared__ float sS[8][128], sQ[8][128];
    int b = blockIdx.z;
    int oBase = blockIdx.x * 128;
    int pBase = blockIdx.y * 128;
    int tid = threadIdx.x;
    int wid = tid >> 5, lane = tid & 31;
    int g = lane >> 2, tig = lane & 3;
    int oW = (wid >> 2) * 64;
    int pW = (wid & 3) * 32;

    const float* Xb = ga.X + (size_t)b * C_ * HW_;
    const unsigned* Wb = ga.Wh;

    int lk2 = tid >> 5;            // 0..7
    int lp0 = (tid & 31) * 4;      // 0..124

    uint4 wR[2];
    float4 xR[2][2];
    auto ldg = [&](int kc) {
        int k0 = kc * 32;
#pragma unroll
        for (int i = 0; i < 2; i++) {
            int idx = tid + i * 256;
            int o = idx >> 2, q = idx & 3;
            wR[i] = *reinterpret_cast<const uint4*>(Wb + (size_t)(oBase + o) * 128 + k0 / 2 + q * 4);
        }
#pragma unroll
        for (int i = 0; i < 2; i++) {
            int kk = k0 + 2 * (lk2 + i * 8);
            xR[i][0] = *reinterpret_cast<const float4*>(Xb + (size_t)kk * HW_ + pBase + lp0);
            xR[i][1] = *reinterpret_cast<const float4*>(Xb + (size_t)(kk + 1) * HW_ + pBase + lp0);
        }
    };
    float stS[4] = {}, stQ[4] = {};
    auto sts = [&](int st) {
        unsigned* sA = sm + st * STG_U;
        unsigned* sB = sA + 128 * SA_U;
#pragma unroll
        for (int i = 0; i < 2; i++) {
            int idx = tid + i * 256;
            int o = idx >> 2, q = idx & 3;
            *reinterpret_cast<uint4*>(sA + o * SA_U + q * 4) = wR[i];
        }
#pragma unroll
        for (int i = 0; i < 2; i++) {
            float4 a = xR[i][0], c = xR[i][1];
            stS[0] += a.x + c.x; stQ[0] += a.x * a.x + c.x * c.x;
            stS[1] += a.y + c.y; stQ[1] += a.y * a.y + c.y * c.y;
            stS[2] += a.z + c.z; stQ[2] += a.z * a.z + c.z * c.z;
            stS[3] += a.w + c.w; stQ[3] += a.w * a.w + c.w * c.w;
            uint4 u;
            u.x = packbf(a.x, c.x);
            u.y = packbf(a.y, c.y);
            u.z = packbf(a.z, c.z);
            u.w = packbf(a.w, c.w);
            *reinterpret_cast<uint4*>(sB + (lk2 + i * 8) * SB_U + lp0) = u;
        }
    };

    float acc[4][4][4] = {};
    ldg(0);
    for (int kc = 0; kc < 8; kc++) {
        sts(kc & 1);
        __syncthreads();
        if (kc < 7) ldg(kc + 1);
        unsigned* sA = sm + (kc & 1) * STG_U;
        unsigned* sB = sA + 128 * SA_U;
#pragma unroll
        for (int s2 = 0; s2 < 16; s2 += 8) {
            unsigned afr[4][4];
#pragma unroll
            for (int mt = 0; mt < 4; mt++) {
                int ro = oW + mt * 16 + g;
                afr[mt][0] = sA[ro * SA_U + s2 + tig];
                afr[mt][1] = sA[(ro + 8) * SA_U + s2 + tig];
                afr[mt][2] = sA[ro * SA_U + s2 + 4 + tig];
                afr[mt][3] = sA[(ro + 8) * SA_U + s2 + 4 + tig];
            }
#pragma unroll
            for (int nt = 0; nt < 4; nt++) {
                int cp = pW + nt * 8 + g;
                unsigned b0 = sB[(s2 + tig) * SB_U + cp];
                unsigned b1 = sB[(s2 + 4 + tig) * SB_U + cp];
#pragma unroll
                for (int mt = 0; mt < 4; mt++)
                    mma_bf16(acc[mt][nt], afr[mt], b0, b1);
            }
        }
        __syncthreads();
    }

    *reinterpret_cast<float4*>(&sS[lk2][lp0]) = make_float4(stS[0], stS[1], stS[2], stS[3]);
    *reinterpret_cast<float4*>(&sQ[lk2][lp0]) = make_float4(stQ[0], stQ[1], stQ[2], stQ[3]);
    __syncthreads();
    float mu[4][2], iv[4][2];
#pragma unroll
    for (int nt = 0; nt < 4; nt++) {
#pragma unroll
        for (int u = 0; u < 2; u++) {
            int pl = pW + nt * 8 + 2 * tig + u;
            float s0 = 0.f, q0 = 0.f;
#pragma unroll
            for (int wrow = 0; wrow < 8; wrow++) { s0 += sS[wrow][pl]; q0 += sQ[wrow][pl]; }
            float m = s0 * (1.f / 256.f);
            float var = q0 * (1.f / 256.f) - m * m;
            mu[nt][u] = m;
            iv[nt][u] = rsqrtf(var + 1e-5f);
        }
    }
#pragma unroll
    for (int mt = 0; mt < 4; mt++) {
        int o0 = oBase + oW + mt * 16 + g;
        int o1 = o0 + 8;
        float rs0 = ga.rsum[o0], b0v = ga.bias[o0];
        float rs1 = ga.rsum[o1], b1v = ga.bias[o1];
#pragma unroll
        for (int nt = 0; nt < 4; nt++) {
            int p = pBase + pW + nt * 8 + 2 * tig;
            bf162 r0 = __floats2bfloat162_rn(
                iv[nt][0] * (acc[mt][nt][0] - mu[nt][0] * rs0) + b0v,
                iv[nt][1] * (acc[mt][nt][1] - mu[nt][1] * rs0) + b0v);
            bf162 r1 = __floats2bfloat162_rn(
                iv[nt][0] * (acc[mt][nt][2] - mu[nt][0] * rs1) + b1v,
                iv[nt][1] * (acc[mt][nt][3] - mu[nt][1] * rs1) + b1v);
            *reinterpret_cast<bf162*>(ga.Yh + ((size_t)b * ga.O + o0) * HW_ + p) = r0;
            *reinterpret_cast<bf162*>(ga.Yh + ((size_t)b * ga.O + o1) * HW_ + p) = r1;
        }
    }
}

// ------------- depthwise 3x3 for q (32-row tile, 8 cols/thread) --------------
__global__ __launch_bounds__(256) void dwq_kernel(const bf16* __restrict__ X,
                                                  const float* __restrict__ w9,
                                                  const float* __restrict__ bias,
                                                  bf16* __restrict__ out,
                                                  float* __restrict__ ssq) {
    __shared__ float si[34][136];
    int b = blockIdx.z, c = blockIdx.y, r0 = blockIdx.x * 32;
    int tid = threadIdx.x;
    const bf16* Xc = X + ((size_t)(b * C_ + c)) * HW_;
    fill_rows<34>(si, Xc, r0, -1, tid);
    float wk[9];
#pragma unroll
    for (int t = 0; t < 9; t++) wk[t] = __ldg(w9 + (size_t)c * 9 + t);
    float bv = __ldg(bias + c);
    __syncthreads();
    bf16* D = out + ((size_t)(b * C_ + c)) * HW_;
    float ss = 0.f;
    int row0 = tid >> 4, s0 = (tid & 15) * 8;
#pragma unroll
    for (int it = 0; it < 2; it++) {
        int row = row0 + it * 16;
        float o[8] = {bv, bv, bv, bv, bv, bv, bv, bv};
#pragma unroll
        for (int dr = 0; dr < 3; dr++)
            stencil8(si[row + dr], s0, wk[dr * 3], wk[dr * 3 + 1], wk[dr * 3 + 2], o);
        *reinterpret_cast<uint4*>(D + (size_t)(r0 + row) * W_ + s0) = f8_to_u4(o);
#pragma unroll
        for (int u = 0; u < 8; u++) ss += o[u] * o[u];
    }
#pragma unroll
    for (int d = 16; d > 0; d >>= 1) ss += __shfl_down_sync(0xffffffffu, ss, d);
    if ((tid & 31) == 0) atomicAdd(&ssq[b * C_ + c], ss);
}

// ---------------- merged kv dwconv + positional branch (16-row tile) ----------
__global__ __launch_bounds__(256) void kvpe_kernel(const float* __restrict__ kvw9,
                                                   const float* __restrict__ kvb,
                                                   const float* __restrict__ pe1,
                                                   const float* __restrict__ pe2) {
    __shared__ float sbuf[(18 + 22 + 20) * 136];
    float (*ski)[136] = reinterpret_cast<float(*)[136]>(sbuf);
    float (*svi)[136] = reinterpret_cast<float(*)[136]>(sbuf + 18 * 136);
    float (*sv)[136]  = reinterpret_cast<float(*)[136]>(sbuf + 40 * 136);
    float (*st1)[136] = svi;
    int b = blockIdx.z, c = blockIdx.y, r0 = blockIdx.x * 16;
    int tid = threadIdx.x;
    const bf16* Kc = g_bufB + ((size_t)(b * 2 * C_ + c)) * HW_;
    const bf16* Vc = g_bufB + ((size_t)(b * 2 * C_ + C_ + c)) * HW_;
    fill_rows<18>(ski, Kc, r0, -1, tid);
    fill_rows<22>(svi, Vc, r0, -3, tid);
    {
        float4 z4 = make_float4(0.f, 0.f, 0.f, 0.f);
        for (int i = tid; i < 20 * 2; i += 256)
            *reinterpret_cast<float4*>(&sv[i >> 1][(i & 1) ? 132 : 0]) = z4;
    }
    float wkk[9], wkv[9], w1[9], w2[9];
#pragma unroll
    for (int t = 0; t < 9; t++) {
        wkk[t] = __ldg(kvw9 + (size_t)c * 9 + t);
        wkv[t] = __ldg(kvw9 + (size_t)(C_ + c) * 9 + t);
        w1[t] = __ldg(pe1 + (size_t)c * 9 + t);
        w2[t] = __ldg(pe2 + (size_t)c * 9 + t);
    }
    float bk = __ldg(kvb + c);
    float bvv = __ldg(kvb + C_ + c);
    __syncthreads();

    int row0 = tid >> 4, s0 = (tid & 15) * 8;

    bf16* Dk = g_k + ((size_t)(b * C_ + c)) * HW_;
    float ss = 0.f;
    {
        float o[8] = {bk, bk, bk, bk, bk, bk, bk, bk};
#pragma unroll
        for (int dr = 0; dr < 3; dr++)
            stencil8(ski[row0 + dr], s0, wkk[dr * 3], wkk[dr * 3 + 1], wkk[dr * 3 + 2], o);
        *reinterpret_cast<uint4*>(Dk + (size_t)(r0 + row0) * W_ + s0) = f8_to_u4(o);
#pragma unroll
        for (int u = 0; u < 8; u++) ss += o[u] * o[u];
    }
#pragma unroll
    for (int d = 16; d > 0; d >>= 1) ss += __shfl_down_sync(0xffffffffu, ss, d);
    if ((tid & 31) == 0) atomicAdd(&g_ss[B_ * C_ + b * C_ + c], ss);

    bf16* Dv = g_v + ((size_t)(b * C_ + c)) * HW_;
    for (int i = tid; i < 20 * 16; i += 256) {
        int row = i >> 4, cc = (i & 15) * 8;
        int gr = r0 - 2 + row;
        float o[8] = {};
        if (gr >= 0 && gr < H_) {
#pragma unroll
            for (int u = 0; u < 8; u++) o[u] = bvv;
#pragma unroll
            for (int dr = 0; dr < 3; dr++)
                stencil8(svi[row + dr], cc, wkv[dr * 3], wkv[dr * 3 + 1], wkv[dr * 3 + 2], o);
        }
        *reinterpret_cast<float4*>(&sv[row][4 + cc]) = make_float4(o[0], o[1], o[2], o[3]);
        *reinterpret_cast<float4*>(&sv[row][8 + cc]) = make_float4(o[4], o[5], o[6], o[7]);
        if (row >= 2 && row < 18)
            *reinterpret_cast<uint4*>(Dv + (size_t)gr * W_ + cc) = f8_to_u4(o);
    }
    __syncthreads();

    for (int i = tid; i < 18 * 16; i += 256) {
        int row = i >> 4, cc = (i & 15) * 8;
        int gr = r0 - 1 + row;
        float o[8] = {};
        if (gr >= 0 && gr < H_) {
#pragma unroll
            for (int dr = 0; dr < 3; dr++)
                stencil8(sv[row + dr], cc, w1[dr * 3], w1[dr * 3 + 1], w1[dr * 3 + 2], o);
#pragma unroll
            for (int u = 0; u < 8; u++) o[u] = gelu_tanh(o[u]);
        }
        *reinterpret_cast<float4*>(&st1[row][4 + cc]) = make_float4(o[0], o[1], o[2], o[3]);
        *reinterpret_cast<float4*>(&st1[row][8 + cc]) = make_float4(o[4], o[5], o[6], o[7]);
    }
    __syncthreads();

    bf16* Dp = g_pe + ((size_t)(b * C_ + c)) * HW_;
    {
        float o[8] = {};
#pragma unroll
        for (int dr = 0; dr < 3; dr++)
            stencil8(st1[row0 + dr], s0, w2[dr * 3], w2[dr * 3 + 1], w2[dr * 3 + 2], o);
        *reinterpret_cast<uint4*>(Dp + (size_t)(r0 + row0) * W_ + s0) = f8_to_u4(o);
    }
}

// ---------------- gram via bf16 mma m16n8k16, split-K=4 ----------------------
__global__ __launch_bounds__(256) void gram_mma() {
    __shared__ float sbuf[8192];
    bf16* sqh = reinterpret_cast<bf16*>(sbuf);
    bf16* skh = sqh + 32 * 136;
    unsigned* squ = reinterpret_cast<unsigned*>(sqh);
    unsigned* sku = reinterpret_cast<unsigned*>(skh);
    int seg = blockIdx.x, h = blockIdx.y, b = blockIdx.z;
    const bf16* Q = g_q + ((size_t)(b * C_ + h * HD_)) * HW_;
    const bf16* K = g_k + ((size_t)(b * C_ + h * HD_)) * HW_;
    int tid = threadIdx.x, wid = tid >> 5, lane = tid & 31;
    int g = lane >> 2, tig = lane & 3;
    float acc[2][4][4] = {};
    int n0 = seg * (HW_ / GSEG);
    int klu = wid * 8;
    for (int ch = 0; ch < (HW_ / GSEG) / 128; ch++) {
        int base = n0 + ch * 128;
        for (int i = tid; i < 32 * 16; i += 256) {
            int row = i >> 4, c8 = (i & 15) * 8;
            *reinterpret_cast<uint4*>(sqh + row * 136 + c8) =
                *reinterpret_cast<const uint4*>(Q + (size_t)row * HW_ + base + c8);
            *reinterpret_cast<uint4*>(skh + row * 136 + c8) =
                *reinterpret_cast<const uint4*>(K + (size_t)row * HW_ + base + c8);
        }
        __syncthreads();
        unsigned afr[2][4];
#pragma unroll
        for (int mt = 0; mt < 2; mt++) {
            int r = mt * 16 + g;
            afr[mt][0] = squ[r * 68 + klu + tig];
            afr[mt][1] = squ[(r + 8) * 68 + klu + tig];
            afr[mt][2] = squ[r * 68 + klu + 4 + tig];
            afr[mt][3] = squ[(r + 8) * 68 + klu + 4 + tig];
        }
#pragma unroll
        for (int nt = 0; nt < 4; nt++) {
            unsigned b0 = sku[(nt * 8 + g) * 68 + klu + tig];
            unsigned b1 = sku[(nt * 8 + g) * 68 + klu + 4 + tig];
#pragma unroll
            for (int mt = 0; mt < 2; mt++)
                mma_bf16(acc[mt][nt], afr[mt], b0, b1);
        }
        __syncthreads();
    }
    float* red = sbuf;
#pragma unroll
    for (int mt = 0; mt < 2; mt++)
#pragma unroll
        for (int nt = 0; nt < 4; nt++) {
            int r = mt * 16 + g, cl = nt * 8 + 2 * tig;
            red[wid * 1024 + r * 32 + cl] = acc[mt][nt][0];
            red[wid * 1024 + r * 32 + cl + 1] = acc[mt][nt][1];
            red[wid * 1024 + (r + 8) * 32 + cl] = acc[mt][nt][2];
            red[wid * 1024 + (r + 8) * 32 + cl + 1] = acc[mt][nt][3];
        }
    __syncthreads();
    float* outp = g_part + ((size_t)(b * HEADS_ + h) * GSEG + seg) * 1024;
    for (int i = tid; i < 1024; i += 256) {
        float s = 0.f;
#pragma unroll
        for (int w = 0; w < 8; w++) s += red[w * 1024 + i];
        outp[i] = s;
    }
}

// ---------------- softmax with fused q/k norm scales + temperature -----------
__global__ void softmax_kernel(const float* __restrict__ temp) {
    int bh = blockIdx.x;
    int b = bh >> 3, h = bh & 7;
    int i = threadIdx.x;
    float qs = 1.f / fmaxf(sqrtf(g_ss[b * C_ + h * HD_ + i]), 1e-12f);
    float T = __ldg(temp + h);
    float v[32];
    float mx = -1e30f;
#pragma unroll 4
    for (int j = 0; j < 32; j++) {
        float s = 0.f;
#pragma unroll
        for (int seg = 0; seg < GSEG; seg++)
            s += g_part[((size_t)bh * GSEG + seg) * 1024 + i * 32 + j];
        float ks = 1.f / fmaxf(sqrtf(g_ss[B_ * C_ + b * C_ + h * HD_ + j]), 1e-12f);
        float val = s * qs * ks * T;
        v[j] = val;
        mx = fmaxf(mx, val);
    }
    float sum = 0.f;
#pragma unroll
    for (int j = 0; j < 32; j++) {
        v[j] = expf(v[j] - mx);
        sum += v[j];
    }
    float inv = 1.f / sum;
#pragma unroll
    for (int j = 0; j < 32; j++) g_attn[bh * 1024 + i * 32 + j] = v[j] * inv;
}

// ------------ M[b] = ao_w @ blockdiag(attn[b]), packed bf16 pairs ------------
__global__ void buildM_kernel(const float* __restrict__ ao_w) {
    int h = blockIdx.x, b = blockIdx.y;
    int tid = threadIdx.x;
    __shared__ float sa[32][33];
#pragma unroll
    for (int t = 0; t < 4; t++) {
        int idx = tid + t * 256;
        sa[idx >> 5][idx & 31] = g_attn[(b * HEADS_ + h) * 1024 + idx];
    }
    __syncthreads();
    float wreg[32];
#pragma unroll
    for (int c = 0; c < 32; c++) wreg[c] = ao_w[(size_t)tid * C_ + h * HD_ + c];
    float m[32];
#pragma unroll 4
    for (int d = 0; d < 32; d++) {
        float s = 0.f;
#pragma unroll
        for (int c = 0; c < 32; c++) s += wreg[c] * sa[c][d];
        m[d] = s;
    }
    unsigned* Mo = g_Mh + ((size_t)(b * C_) + tid) * 128 + h * 16;
#pragma unroll
    for (int j = 0; j < 16; j++) Mo[j] = packbf(m[2 * j], m[2 * j + 1]);
}

// ======= final GEMM: out = M@v + ao_b + pemb + hx (bf16 m16n8k16) ============
__global__ __launch_bounds__(256, 2) void gemm_outh_kernel(const float* __restrict__ bias,
                                                           const float* __restrict__ hx,
                                                           float* __restrict__ out) {
    __shared__ unsigned sm[2 * STG_U];
    int b = blockIdx.z;
    int oBase = blockIdx.x * 128;
    int pBase = blockIdx.y * 128;
    int tid = threadIdx.x;
    int wid = tid >> 5, lane = tid & 31;
    int g = lane >> 2, tig = lane & 3;
    int oW = (wid >> 2) * 64;
    int pW = (wid & 3) * 32;

    const unsigned* Mb = g_Mh + (size_t)b * C_ * 128;
    const bf16* Vb = g_v + (size_t)b * C_ * HW_;

    int lk2 = tid >> 4;            // 0..15
    int lp8 = (tid & 15) * 8;      // 0..120

    uint4 aR[2];
    uint4 vA, vB;
    auto ldg = [&](int kc) {
        int k0 = kc * 32;
#pragma unroll
        for (int i = 0; i < 2; i++) {
            int idx = tid + i * 256;
            int o = idx >> 2, q = idx & 3;
            aR[i] = *reinterpret_cast<const uint4*>(Mb + (size_t)(oBase + o) * 128 + k0 / 2 + q * 4);
        }
        int kk = k0 + 2 * lk2;
        vA = *reinterpret_cast<const uint4*>(Vb + (size_t)kk * HW_ + pBase + lp8);
        vB = *reinterpret_cast<const uint4*>(Vb + (size_t)(kk + 1) * HW_ + pBase + lp8);
    };
    auto sts = [&](int st) {
        unsigned* sA = sm + st * STG_U;
        unsigned* sB = sA + 128 * SA_U;
#pragma unroll
        for (int i = 0; i < 2; i++) {
            int idx = tid + i * 256;
            int o = idx >> 2, q = idx & 3;
            *reinterpret_cast<uint4*>(sA + o * SA_U + q * 4) = aR[i];
        }
        // interleave rows k, k+1 per pixel: out uint j = (lowhalf_j(vA), lowhalf_j(vB))
        uint4 o0, o1;
        o0.x = __byte_perm(vA.x, vB.x, 0x5410);
        o0.y = __byte_perm(vA.x, vB.x, 0x7632);
        o0.z = __byte_perm(vA.y, vB.y, 0x5410);
        o0.w = __byte_perm(vA.y, vB.y, 0x7632);
        o1.x = __byte_perm(vA.z, vB.z, 0x5410);
        o1.y = __byte_perm(vA.z, vB.z, 0x7632);
        o1.z = __byte_perm(vA.w, vB.w, 0x5410);
        o1.w = __byte_perm(vA.w, vB.w, 0x7632);
        *reinterpret_cast<uint4*>(sB + lk2 * SB_U + lp8) = o0;
        *reinterpret_cast<uint4*>(sB + lk2 * SB_U + lp8 + 4) = o1;
    };

    float acc[4][4][4] = {};
    ldg(0);
    for (int kc = 0; kc < 8; kc++) {
        sts(kc & 1);
        __syncthreads();
        if (kc < 7) ldg(kc + 1);
        unsigned* sA = sm + (kc & 1) * STG_U;
        unsigned* sB = sA + 128 * SA_U;
#pragma unroll
        for (int s2 = 0; s2 < 16; s2 += 8) {
            unsigned afr[4][4];
#pragma unroll
            for (int mt = 0; mt < 4; mt++) {
                int ro = oW + mt * 16 + g;
                afr[mt][0] = sA[ro * SA_U + s2 + tig];
                afr[mt][1] = sA[(ro + 8) * SA_U + s2 + tig];
                afr[mt][2] = sA[ro * SA_U + s2 + 4 + tig];
                afr[mt][3] = sA[(ro + 8) * SA_U + s2 + 4 + tig];
            }
#pragma unroll
            for (int nt = 0; nt < 4; nt++) {
                int cp = pW + nt * 8 + g;
                unsigned b0 = sB[(s2 + tig) * SB_U + cp];
                unsigned b1 = sB[(s2 + 4 + tig) * SB_U + cp];
#pragma unroll
                for (int mt = 0; mt < 4; mt++)
                    mma_bf16(acc[mt][nt], afr[mt], b0, b1);
            }
        }
        __syncthreads();
    }

    const bf16* PEb = g_pe + (size_t)b * C_ * HW_;
    const float* HXb = hx + (size_t)b * C_ * HW_;
#pragma unroll
    for (int mt = 0; mt < 4; mt++) {
        int o0 = oBase + oW + mt * 16 + g;
        int o1 = o0 + 8;
        float b0v = bias[o0], b1v = bias[o1];
#pragma unroll
        for (int nt = 0; nt < 4; nt++) {
            int p = pBase + pW + nt * 8 + 2 * tig;
            float2 h0 = *reinterpret_cast<const float2*>(HXb + (size_t)o0 * HW_ + p);
            float2 h1 = *reinterpret_cast<const float2*>(HXb + (size_t)o1 * HW_ + p);
            float2 pf0 = __bfloat1622float2(
                *reinterpret_cast<const bf162*>(PEb + (size_t)o0 * HW_ + p));
            float2 pf1 = __bfloat1622float2(
                *reinterpret_cast<const bf162*>(PEb + (size_t)o1 * HW_ + p));
            float2 r0, r1;
            r0.x = acc[mt][nt][0] + b0v + pf0.x + h0.x;
            r0.y = acc[mt][nt][1] + b0v + pf0.y + h0.y;
            r1.x = acc[mt][nt][2] + b1v + pf1.x + h1.x;
            r1.y = acc[mt][nt][3] + b1v + pf1.y + h1.y;
            *reinterpret_cast<float2*>(out + ((size_t)b * C_ + o0) * HW_ + p) = r0;
            *reinterpret_cast<float2*>(out + ((size_t)b * C_ + o1) * HW_ + p) = r1;
        }
    }
}

// -----------------------------------------------------------------------------
extern "C" void kernel_launch(void* const* d_in, const int* in_sizes, int n_in,
                              void* d_out, int out_size) {
    const float* x = (const float*)d_in[0];
    const float* hx = (const float*)d_in[1];
    const float* ln1_w = (const float*)d_in[2];
    const float* ln1_b = (const float*)d_in[3];
    const float* ln2_w = (const float*)d_in[4];
    const float* ln2_b = (const float*)d_in[5];
    const float* q_w = (const float*)d_in[6];
    const float* q_b = (const float*)d_in[7];
    const float* q_dw_w = (const float*)d_in[8];
    const float* q_dw_b = (const float*)d_in[9];
    const float* kv_w = (const float*)d_in[10];
    const float* kv_b = (const float*)d_in[11];
    const float* kv_dw_w = (const float*)d_in[12];
    const float* kv_dw_b = (const float*)d_in[13];
    const float* ao_w = (const float*)d_in[14];
    const float* ao_b = (const float*)d_in[15];
    const float* pe1_w = (const float*)d_in[16];
    const float* pe2_w = (const float*)d_in[17];
    const float* temperature = (const float*)d_in[18];
    float* out = (float*)d_out;

    unsigned *p_Wqh, *p_Wkvh;
    float *p_bq, *p_bkv, *p_rsq, *p_rskv, *p_ss;
    bf16 *p_bufA, *p_bufB, *p_q;
    cudaGetSymbolAddress((void**)&p_Wqh, g_Wqh);
    cudaGetSymbolAddress((void**)&p_Wkvh, g_Wkvh);
    cudaGetSymbolAddress((void**)&p_bq, g_bq);
    cudaGetSymbolAddress((void**)&p_bkv, g_bkv);
    cudaGetSymbolAddress((void**)&p_rsq, g_rsq);
    cudaGetSymbolAddress((void**)&p_rskv, g_rskv);
    cudaGetSymbolAddress((void**)&p_ss, g_ss);
    cudaGetSymbolAddress((void**)&p_bufA, g_bufA);
    cudaGetSymbolAddress((void**)&p_bufB, g_bufB);
    cudaGetSymbolAddress((void**)&p_q, g_q);

    // 1. fold LN into weights (pack bf16 pairs); zero sumsq accumulators
    prep_w_kernel<<<3 * C_, 256>>>(q_w, q_b, ln1_w, ln1_b, kv_w, kv_b, ln2_w, ln2_b);

    // 2. q_pre = conv1x1(ln(x)) -> bufA ; kv_pre = conv1x1(ln(hx)) -> bufB
    {
        GemmArgs ga{};
        ga.X = x; ga.Wh = p_Wqh; ga.bias = p_bq; ga.rsum = p_rsq;
        ga.Yh = p_bufA; ga.O = C_;
        gemm_lnh_kernel<<<dim3(C_ / 128, HW_ / 128, B_), 256>>>(ga);
    }
    {
        GemmArgs ga{};
        ga.X = hx; ga.Wh = p_Wkvh; ga.bias = p_bkv; ga.rsum = p_rskv;
        ga.Yh = p_bufB; ga.O = 2 * C_;
        gemm_lnh_kernel<<<dim3(2 * C_ / 128, HW_ / 128, B_), 256>>>(ga);
    }

    // 3. q dwconv -> g_q (+sumsq)
    dwq_kernel<<<dim3(4, C_, B_), 256>>>(p_bufA, q_dw_w, q_dw_b, p_q, p_ss);

    // 4. merged kv dwconv + positional branch -> g_k, g_v, g_pe
    kvpe_kernel<<<dim3(8, C_, B_), 256>>>(kv_dw_w, kv_dw_b, pe1_w, pe2_w);

    // 5. gram (bf16 mma, split-K=4), softmax with fused norms
    gram_mma<<<dim3(GSEG, HEADS_, B_), 256>>>();
    softmax_kernel<<<B_ * HEADS_, 32>>>(temperature);

    // 6. fold attn into output projection; final fused GEMM
    buildM_kernel<<<dim3(HEADS_, B_), 256>>>(ao_w);
    gemm_outh_kernel<<<dim3(C_ / 128, HW_ / 128, B_), 256>>>(ao_b, hx, out);
}

// round 8
// speedup vs baseline: 1.1372x; 1.0148x over previous
#include <cuda_runtime.h>
#include <cuda_bf16.h>
#include <math.h>
#include <stdint.h>

#define B_ 8
#define C_ 256
#define H_ 128
#define W_ 128
#define HW_ 16384
#define HEADS_ 8
#define HD_ 32
#define GSEG 4

typedef __nv_bfloat16 bf16;
typedef __nv_bfloat162 bf162;

// ---------------- scratch (device globals; no allocation allowed) ------------
__device__ bf16 g_bufA[B_ * C_ * HW_];           // q_pre
__device__ bf16 g_bufB[B_ * 2 * C_ * HW_];       // kv_pre
__device__ bf16 g_q[B_ * C_ * HW_];
__device__ bf16 g_k[B_ * C_ * HW_];
__device__ bf16 g_v[B_ * C_ * HW_];
__device__ bf16 g_pe[B_ * C_ * HW_];             // pemb (WITHOUT hx)
__device__ unsigned g_Wqh[C_ * 128];             // bf16-pair packed folded weights
__device__ unsigned g_Wkvh[2 * C_ * 128];
__device__ unsigned g_Mh[B_ * C_ * 128];         // packed M = ao_w @ blockdiag(attn)
__device__ float g_bq[C_];
__device__ float g_bkv[2 * C_];
__device__ float g_rsq[C_];
__device__ float g_rskv[2 * C_];
__device__ float g_ss[2 * B_ * C_];
__device__ float g_part[B_ * HEADS_ * GSEG * 1024];
__device__ float g_attn[B_ * HEADS_ * 1024];

// ---------------- helpers ------------------------------------------------
__device__ __forceinline__ void mma_bf16(float* c, const unsigned* a, unsigned b0, unsigned b1) {
    asm volatile(
        "mma.sync.aligned.m16n8k16.row.col.f32.bf16.bf16.f32 "
        "{%0,%1,%2,%3}, {%4,%5,%6,%7}, {%8,%9}, {%0,%1,%2,%3};\n"
        : "+f"(c[0]), "+f"(c[1]), "+f"(c[2]), "+f"(c[3])
        : "r"(a[0]), "r"(a[1]), "r"(a[2]), "r"(a[3]), "r"(b0), "r"(b1));
}
__device__ __forceinline__ unsigned packbf(float lo, float hi) {
    bf162 t = __floats2bfloat162_rn(lo, hi);
    return *reinterpret_cast<unsigned*>(&t);
}
__device__ __forceinline__ float gelu_tanh(float s) {
    float x3 = s * s * s;
    return 0.5f * s * (1.f + tanhf(0.7978845608028654f * (s + 0.044715f * x3)));
}
__device__ __forceinline__ void u4_to_f8(uint4 u, float4& lo, float4& hi) {
    bf162 h0 = *reinterpret_cast<bf162*>(&u.x);
    bf162 h1 = *reinterpret_cast<bf162*>(&u.y);
    bf162 h2 = *reinterpret_cast<bf162*>(&u.z);
    bf162 h3 = *reinterpret_cast<bf162*>(&u.w);
    float2 f0 = __bfloat1622float2(h0), f1 = __bfloat1622float2(h1);
    float2 f2 = __bfloat1622float2(h2), f3 = __bfloat1622float2(h3);
    lo = make_float4(f0.x, f0.y, f1.x, f1.y);
    hi = make_float4(f2.x, f2.y, f3.x, f3.y);
}
__device__ __forceinline__ uint4 f8_to_u4(const float* o) {
    uint4 r;
    r.x = packbf(o[0], o[1]);
    r.y = packbf(o[2], o[3]);
    r.z = packbf(o[4], o[5]);
    r.w = packbf(o[6], o[7]);
    return r;
}

// 8-wide 3-tap over a padded smem row (data at +4; pads zero at 0..3 / 132..135)
__device__ __forceinline__ void stencil8(const float* R, int s, float w0, float w1, float w2,
                                         float* o) {
    float4 m0 = *reinterpret_cast<const float4*>(R + 4 + s);
    float4 m1 = *reinterpret_cast<const float4*>(R + 8 + s);
    float l = R[3 + s], r = R[12 + s];
    o[0] += w0 * l    + w1 * m0.x + w2 * m0.y;
    o[1] += w0 * m0.x + w1 * m0.y + w2 * m0.z;
    o[2] += w0 * m0.y + w1 * m0.z + w2 * m0.w;
    o[3] += w0 * m0.z + w1 * m0.w + w2 * m1.x;
    o[4] += w0 * m0.w + w1 * m1.x + w2 * m1.y;
    o[5] += w0 * m1.x + w1 * m1.y + w2 * m1.z;
    o[6] += w0 * m1.y + w1 * m1.z + w2 * m1.w;
    o[7] += w0 * m1.z + w1 * m1.w + w2 * r;
}

// single-pass fill of N padded rows from bf16 global (row gr = r0+roff+row; OOB -> zeros)
template <int NROWS>
__device__ __forceinline__ void fill_rows(float (*dst)[136], const bf16* src, int r0, int roff,
                                          int tid) {
    float4 z4 = make_float4(0.f, 0.f, 0.f, 0.f);
    for (int i = tid; i < NROWS * 16; i += 256) {
        int row = i >> 4, c8 = (i & 15) * 8;
        int gr = r0 + roff + row;
        float4 lo = z4, hi = z4;
        if (gr >= 0 && gr < H_) {
            uint4 u = *reinterpret_cast<const uint4*>(src + (size_t)gr * W_ + c8);
            u4_to_f8(u, lo, hi);
        }
        *reinterpret_cast<float4*>(&dst[row][4 + c8]) = lo;
        *reinterpret_cast<float4*>(&dst[row][8 + c8]) = hi;
    }
    for (int i = tid; i < NROWS * 2; i += 256) {
        int row = i >> 1;
        *reinterpret_cast<float4*>(&dst[row][(i & 1) ? 132 : 0]) = z4;
    }
}

// ---------------- weight prep: fold LN gamma/beta, pack to bf16 pairs --------
__global__ void prep_w_kernel(const float* __restrict__ qw, const float* __restrict__ qb,
                              const float* __restrict__ ln1w, const float* __restrict__ ln1b,
                              const float* __restrict__ kvw, const float* __restrict__ kvb,
                              const float* __restrict__ ln2w, const float* __restrict__ ln2b) {
    int r = blockIdx.x;
    int tid = threadIdx.x;
    if (r < 16) g_ss[r * 256 + tid] = 0.f;
    const float *w, *lnw, *lnb;
    float cb;
    unsigned* dWh;
    float *dB, *dR;
    if (r < C_) {
        int o = r;
        w = qw + (size_t)o * C_; lnw = ln1w; lnb = ln1b; cb = qb[o];
        dWh = g_Wqh + (size_t)o * 128; dB = g_bq + o; dR = g_rsq + o;
    } else {
        int o = r - C_;
        w = kvw + (size_t)o * C_; lnw = ln2w; lnb = ln2b; cb = kvb[o];
        dWh = g_Wkvh + (size_t)o * 128; dB = g_bkv + o; dR = g_rskv + o;
    }
    float wv = w[tid];
    float we = wv * lnw[tid];
    float we_r = __bfloat162float(__float2bfloat16(we));
    __shared__ float shw[256], sh1[256], sh2[256];
    shw[tid] = we_r;
    sh1[tid] = we_r;
    sh2[tid] = wv * lnb[tid];
    __syncthreads();
    if (tid < 128) dWh[tid] = packbf(shw[2 * tid], shw[2 * tid + 1]);
    for (int s = 128; s > 0; s >>= 1) {
        if (tid < s) { sh1[tid] += sh1[tid + s]; sh2[tid] += sh2[tid + s]; }
        __syncthreads();
    }
    if (tid == 0) { *dR = sh1[0]; *dB = cb + sh2[0]; }
}

// ========= LN-fused GEMM: bf16 m16n8k16, fp32 X -> bf16 pack on the fly ======
struct GemmArgs {
    const float* X;
    const unsigned* Wh;
    const float* bias;
    const float* rsum;
    bf16* Yh;
    int O;
};

#define SA_U 20
#define SB_U 136
#define STG_U (128 * SA_U + 16 * SB_U)   // 4736 uints / stage

__global__ __launch_bounds__(256, 2) void gemm_lnh_kernel(GemmArgs ga) {
    __shared__ unsigned sm[2 * STG_U];
    __shared__ float sS[8][128], sQ[8][128];
    int b = blockIdx.z;
    int oBase = blockIdx.x * 128;
    int pBase = blockIdx.y * 128;
    int tid = threadIdx.x;
    int wid = tid >> 5, lane = tid & 31;
    int g = lane >> 2, tig = lane & 3;
    int oW = (wid >> 2) * 64;
    int pW = (wid & 3) * 32;

    const float* Xb = ga.X + (size_t)b * C_ * HW_;
    const unsigned* Wb = ga.Wh;

    int lk2 = tid >> 5;
    int lp0 = (tid & 31) * 4;

    uint4 wR[2];
    float4 xR[2][2];
    auto ldg = [&](int kc) {
        int k0 = kc * 32;
#pragma unroll
        for (int i = 0; i < 2; i++) {
            int idx = tid + i * 256;
            int o = idx >> 2, q = idx & 3;
            wR[i] = *reinterpret_cast<const uint4*>(Wb + (size_t)(oBase + o) * 128 + k0 / 2 + q * 4);
        }
#pragma unroll
        for (int i = 0; i < 2; i++) {
            int kk = k0 + 2 * (lk2 + i * 8);
            xR[i][0] = *reinterpret_cast<const float4*>(Xb + (size_t)kk * HW_ + pBase + lp0);
            xR[i][1] = *reinterpret_cast<const float4*>(Xb + (size_t)(kk + 1) * HW_ + pBase + lp0);
        }
    };
    float stS[4] = {}, stQ[4] = {};
    auto sts = [&](int st) {
        unsigned* sA = sm + st * STG_U;
        unsigned* sB = sA + 128 * SA_U;
#pragma unroll
        for (int i = 0; i < 2; i++) {
            int idx = tid + i * 256;
            int o = idx >> 2, q = idx & 3;
            *reinterpret_cast<uint4*>(sA + o * SA_U + q * 4) = wR[i];
        }
#pragma unroll
        for (int i = 0; i < 2; i++) {
            float4 a = xR[i][0], c = xR[i][1];
            stS[0] += a.x + c.x; stQ[0] += a.x * a.x + c.x * c.x;
            stS[1] += a.y + c.y; stQ[1] += a.y * a.y + c.y * c.y;
            stS[2] += a.z + c.z; stQ[2] += a.z * a.z + c.z * c.z;
            stS[3] += a.w + c.w; stQ[3] += a.w * a.w + c.w * c.w;
            uint4 u;
            u.x = packbf(a.x, c.x);
            u.y = packbf(a.y, c.y);
            u.z = packbf(a.z, c.z);
            u.w = packbf(a.w, c.w);
            *reinterpret_cast<uint4*>(sB + (lk2 + i * 8) * SB_U + lp0) = u;
        }
    };

    float acc[4][4][4] = {};
    ldg(0);
    for (int kc = 0; kc < 8; kc++) {
        sts(kc & 1);
        __syncthreads();
        if (kc < 7) ldg(kc + 1);
        unsigned* sA = sm + (kc & 1) * STG_U;
        unsigned* sB = sA + 128 * SA_U;
#pragma unroll
        for (int s2 = 0; s2 < 16; s2 += 8) {
            unsigned afr[4][4];
#pragma unroll
            for (int mt = 0; mt < 4; mt++) {
                int ro = oW + mt * 16 + g;
                afr[mt][0] = sA[ro * SA_U + s2 + tig];
                afr[mt][1] = sA[(ro + 8) * SA_U + s2 + tig];
                afr[mt][2] = sA[ro * SA_U + s2 + 4 + tig];
                afr[mt][3] = sA[(ro + 8) * SA_U + s2 + 4 + tig];
            }
#pragma unroll
            for (int nt = 0; nt < 4; nt++) {
                int cp = pW + nt * 8 + g;
                unsigned b0 = sB[(s2 + tig) * SB_U + cp];
                unsigned b1 = sB[(s2 + 4 + tig) * SB_U + cp];
#pragma unroll
                for (int mt = 0; mt < 4; mt++)
                    mma_bf16(acc[mt][nt], afr[mt], b0, b1);
            }
        }
        __syncthreads();
    }

    *reinterpret_cast<float4*>(&sS[lk2][lp0]) = make_float4(stS[0], stS[1], stS[2], stS[3]);
    *reinterpret_cast<float4*>(&sQ[lk2][lp0]) = make_float4(stQ[0], stQ[1], stQ[2], stQ[3]);
    __syncthreads();
    float mu[4][2], iv[4][2];
#pragma unroll
    for (int nt = 0; nt < 4; nt++) {
#pragma unroll
        for (int u = 0; u < 2; u++) {
            int pl = pW + nt * 8 + 2 * tig + u;
            float s0 = 0.f, q0 = 0.f;
#pragma unroll
            for (int wrow = 0; wrow < 8; wrow++) { s0 += sS[wrow][pl]; q0 += sQ[wrow][pl]; }
            float m = s0 * (1.f / 256.f);
            float var = q0 * (1.f / 256.f) - m * m;
            mu[nt][u] = m;
            iv[nt][u] = rsqrtf(var + 1e-5f);
        }
    }
#pragma unroll
    for (int mt = 0; mt < 4; mt++) {
        int o0 = oBase + oW + mt * 16 + g;
        int o1 = o0 + 8;
        float rs0 = ga.rsum[o0], b0v = ga.bias[o0];
        float rs1 = ga.rsum[o1], b1v = ga.bias[o1];
#pragma unroll
        for (int nt = 0; nt < 4; nt++) {
            int p = pBase + pW + nt * 8 + 2 * tig;
            bf162 r0 = __floats2bfloat162_rn(
                iv[nt][0] * (acc[mt][nt][0] - mu[nt][0] * rs0) + b0v,
                iv[nt][1] * (acc[mt][nt][1] - mu[nt][1] * rs0) + b0v);
            bf162 r1 = __floats2bfloat162_rn(
                iv[nt][0] * (acc[mt][nt][2] - mu[nt][0] * rs1) + b1v,
                iv[nt][1] * (acc[mt][nt][3] - mu[nt][1] * rs1) + b1v);
            *reinterpret_cast<bf162*>(ga.Yh + ((size_t)b * ga.O + o0) * HW_ + p) = r0;
            *reinterpret_cast<bf162*>(ga.Yh + ((size_t)b * ga.O + o1) * HW_ + p) = r1;
        }
    }
}

// ===== register-strip depthwise 3x3 (+bias, +sumsq), no smem ==================
// thread: 8x8 output patch; streams 10 input rows through registers.
__global__ __launch_bounds__(256) void dw_reg_kernel(const bf16* __restrict__ X,
                                                     int chanTot, int wOff,
                                                     const float* __restrict__ w9,
                                                     const float* __restrict__ bias,
                                                     bf16* __restrict__ out,
                                                     float* __restrict__ ssq) {
    int b = blockIdx.z, c = blockIdx.y;
    int tid = threadIdx.x;
    int cg = tid & 15, rg = tid >> 4;
    int c0 = cg * 8, r0 = rg * 8;
    const bf16* Xc = X + ((size_t)(b * chanTot + c)) * HW_;
    float wk[9];
#pragma unroll
    for (int t = 0; t < 9; t++) wk[t] = __ldg(w9 + (size_t)(wOff + c) * 9 + t);
    float bv = __ldg(bias + wOff + c);
    float acc[8][8];
#pragma unroll
    for (int r = 0; r < 8; r++)
#pragma unroll
        for (int u = 0; u < 8; u++) acc[r][u] = bv;
#pragma unroll
    for (int t = 0; t < 10; t++) {
        int ir = r0 - 1 + t;
        float f[10];
#pragma unroll
        for (int u = 0; u < 10; u++) f[u] = 0.f;
        if (ir >= 0 && ir < H_) {
            uint4 u4 = *reinterpret_cast<const uint4*>(Xc + (size_t)ir * W_ + c0);
            float4 lo, hi;
            u4_to_f8(u4, lo, hi);
            f[1] = lo.x; f[2] = lo.y; f[3] = lo.z; f[4] = lo.w;
            f[5] = hi.x; f[6] = hi.y; f[7] = hi.z; f[8] = hi.w;
            if (c0 > 0) f[0] = __bfloat162float(__ldg(Xc + (size_t)ir * W_ + c0 - 1));
            if (c0 + 8 < W_) f[9] = __bfloat162float(__ldg(Xc + (size_t)ir * W_ + c0 + 8));
        }
        if (t >= 2) {
#pragma unroll
            for (int u = 0; u < 8; u++)
                acc[t - 2][u] += wk[6] * f[u] + wk[7] * f[u + 1] + wk[8] * f[u + 2];
        }
        if (t >= 1 && t <= 8) {
#pragma unroll
            for (int u = 0; u < 8; u++)
                acc[t - 1][u] += wk[3] * f[u] + wk[4] * f[u + 1] + wk[5] * f[u + 2];
        }
        if (t <= 7) {
#pragma unroll
            for (int u = 0; u < 8; u++)
                acc[t][u] += wk[0] * f[u] + wk[1] * f[u + 1] + wk[2] * f[u + 2];
        }
    }
    bf16* D = out + ((size_t)(b * C_ + c)) * HW_;
    float ss = 0.f;
#pragma unroll
    for (int r = 0; r < 8; r++) {
        *reinterpret_cast<uint4*>(D + (size_t)(r0 + r) * W_ + c0) = f8_to_u4(acc[r]);
#pragma unroll
        for (int u = 0; u < 8; u++) ss += acc[r][u] * acc[r][u];
    }
#pragma unroll
    for (int d = 16; d > 0; d >>= 1) ss += __shfl_down_sync(0xffffffffu, ss, d);
    if ((tid & 31) == 0) atomicAdd(&ssq[b * C_ + c], ss);
}

// ------------- v dwconv + positional branch (k handled by dw_reg) -------------
__global__ __launch_bounds__(256) void vpe_kernel(const float* __restrict__ kvw9,
                                                  const float* __restrict__ kvb,
                                                  const float* __restrict__ pe1,
                                                  const float* __restrict__ pe2) {
    __shared__ float sbuf[(22 + 20) * 136];
    float (*svi)[136] = reinterpret_cast<float(*)[136]>(sbuf);            // 22 rows
    float (*sv)[136]  = reinterpret_cast<float(*)[136]>(sbuf + 22 * 136); // 20 rows
    float (*st1)[136] = svi;                                              // alias (18 rows)
    int b = blockIdx.z, c = blockIdx.y, r0 = blockIdx.x * 16;
    int tid = threadIdx.x;
    const bf16* Vc = g_bufB + ((size_t)(b * 2 * C_ + C_ + c)) * HW_;
    fill_rows<22>(svi, Vc, r0, -3, tid);
    {
        float4 z4 = make_float4(0.f, 0.f, 0.f, 0.f);
        for (int i = tid; i < 20 * 2; i += 256)
            *reinterpret_cast<float4*>(&sv[i >> 1][(i & 1) ? 132 : 0]) = z4;
    }
    float wkv[9], w1[9], w2[9];
#pragma unroll
    for (int t = 0; t < 9; t++) {
        wkv[t] = __ldg(kvw9 + (size_t)(C_ + c) * 9 + t);
        w1[t] = __ldg(pe1 + (size_t)c * 9 + t);
        w2[t] = __ldg(pe2 + (size_t)c * 9 + t);
    }
    float bvv = __ldg(kvb + C_ + c);
    __syncthreads();

    int row0 = tid >> 4, s0 = (tid & 15) * 8;

    bf16* Dv = g_v + ((size_t)(b * C_ + c)) * HW_;
    for (int i = tid; i < 20 * 16; i += 256) {
        int row = i >> 4, cc = (i & 15) * 8;
        int gr = r0 - 2 + row;
        float o[8] = {};
        if (gr >= 0 && gr < H_) {
#pragma unroll
            for (int u = 0; u < 8; u++) o[u] = bvv;
#pragma unroll
            for (int dr = 0; dr < 3; dr++)
                stencil8(svi[row + dr], cc, wkv[dr * 3], wkv[dr * 3 + 1], wkv[dr * 3 + 2], o);
        }
        *reinterpret_cast<float4*>(&sv[row][4 + cc]) = make_float4(o[0], o[1], o[2], o[3]);
        *reinterpret_cast<float4*>(&sv[row][8 + cc]) = make_float4(o[4], o[5], o[6], o[7]);
        if (row >= 2 && row < 18)
            *reinterpret_cast<uint4*>(Dv + (size_t)gr * W_ + cc) = f8_to_u4(o);
    }
    __syncthreads();

    for (int i = tid; i < 18 * 16; i += 256) {
        int row = i >> 4, cc = (i & 15) * 8;
        int gr = r0 - 1 + row;
        float o[8] = {};
        if (gr >= 0 && gr < H_) {
#pragma unroll
            for (int dr = 0; dr < 3; dr++)
                stencil8(sv[row + dr], cc, w1[dr * 3], w1[dr * 3 + 1], w1[dr * 3 + 2], o);
#pragma unroll
            for (int u = 0; u < 8; u++) o[u] = gelu_tanh(o[u]);
        }
        *reinterpret_cast<float4*>(&st1[row][4 + cc]) = make_float4(o[0], o[1], o[2], o[3]);
        *reinterpret_cast<float4*>(&st1[row][8 + cc]) = make_float4(o[4], o[5], o[6], o[7]);
    }
    __syncthreads();

    bf16* Dp = g_pe + ((size_t)(b * C_ + c)) * HW_;
    {
        float o[8] = {};
#pragma unroll
        for (int dr = 0; dr < 3; dr++)
            stencil8(st1[row0 + dr], s0, w2[dr * 3], w2[dr * 3 + 1], w2[dr * 3 + 2], o);
        *reinterpret_cast<uint4*>(Dp + (size_t)(r0 + row0) * W_ + s0) = f8_to_u4(o);
    }
}

// ---------------- gram via bf16 mma m16n8k16, split-K=4 ----------------------
__global__ __launch_bounds__(256) void gram_mma() {
    __shared__ float sbuf[8192];
    bf16* sqh = reinterpret_cast<bf16*>(sbuf);
    bf16* skh = sqh + 32 * 136;
    unsigned* squ = reinterpret_cast<unsigned*>(sqh);
    unsigned* sku = reinterpret_cast<unsigned*>(skh);
    int seg = blockIdx.x, h = blockIdx.y, b = blockIdx.z;
    const bf16* Q = g_q + ((size_t)(b * C_ + h * HD_)) * HW_;
    const bf16* K = g_k + ((size_t)(b * C_ + h * HD_)) * HW_;
    int tid = threadIdx.x, wid = tid >> 5, lane = tid & 31;
    int g = lane >> 2, tig = lane & 3;
    float acc[2][4][4] = {};
    int n0 = seg * (HW_ / GSEG);
    int klu = wid * 8;
    for (int ch = 0; ch < (HW_ / GSEG) / 128; ch++) {
        int base = n0 + ch * 128;
        for (int i = tid; i < 32 * 16; i += 256) {
            int row = i >> 4, c8 = (i & 15) * 8;
            *reinterpret_cast<uint4*>(sqh + row * 136 + c8) =
                *reinterpret_cast<const uint4*>(Q + (size_t)row * HW_ + base + c8);
            *reinterpret_cast<uint4*>(skh + row * 136 + c8) =
                *reinterpret_cast<const uint4*>(K + (size_t)row * HW_ + base + c8);
        }
        __syncthreads();
        unsigned afr[2][4];
#pragma unroll
        for (int mt = 0; mt < 2; mt++) {
            int r = mt * 16 + g;
            afr[mt][0] = squ[r * 68 + klu + tig];
            afr[mt][1] = squ[(r + 8) * 68 + klu + tig];
            afr[mt][2] = squ[r * 68 + klu + 4 + tig];
            afr[mt][3] = squ[(r + 8) * 68 + klu + 4 + tig];
        }
#pragma unroll
        for (int nt = 0; nt < 4; nt++) {
            unsigned b0 = sku[(nt * 8 + g) * 68 + klu + tig];
            unsigned b1 = sku[(nt * 8 + g) * 68 + klu + 4 + tig];
#pragma unroll
            for (int mt = 0; mt < 2; mt++)
                mma_bf16(acc[mt][nt], afr[mt], b0, b1);
        }
        __syncthreads();
    }
    float* red = sbuf;
#pragma unroll
    for (int mt = 0; mt < 2; mt++)
#pragma unroll
        for (int nt = 0; nt < 4; nt++) {
            int r = mt * 16 + g, cl = nt * 8 + 2 * tig;
            red[wid * 1024 + r * 32 + cl] = acc[mt][nt][0];
            red[wid * 1024 + r * 32 + cl + 1] = acc[mt][nt][1];
            red[wid * 1024 + (r + 8) * 32 + cl] = acc[mt][nt][2];
            red[wid * 1024 + (r + 8) * 32 + cl + 1] = acc[mt][nt][3];
        }
    __syncthreads();
    float* outp = g_part + ((size_t)(b * HEADS_ + h) * GSEG + seg) * 1024;
    for (int i = tid; i < 1024; i += 256) {
        float s = 0.f;
#pragma unroll
        for (int w = 0; w < 8; w++) s += red[w * 1024 + i];
        outp[i] = s;
    }
}

// ---------------- softmax with fused q/k norm scales + temperature -----------
__global__ void softmax_kernel(const float* __restrict__ temp) {
    int bh = blockIdx.x;
    int b = bh >> 3, h = bh & 7;
    int i = threadIdx.x;
    float qs = 1.f / fmaxf(sqrtf(g_ss[b * C_ + h * HD_ + i]), 1e-12f);
    float T = __ldg(temp + h);
    float v[32];
    float mx = -1e30f;
#pragma unroll 4
    for (int j = 0; j < 32; j++) {
        float s = 0.f;
#pragma unroll
        for (int seg = 0; seg < GSEG; seg++)
            s += g_part[((size_t)bh * GSEG + seg) * 1024 + i * 32 + j];
        float ks = 1.f / fmaxf(sqrtf(g_ss[B_ * C_ + b * C_ + h * HD_ + j]), 1e-12f);
        float val = s * qs * ks * T;
        v[j] = val;
        mx = fmaxf(mx, val);
    }
    float sum = 0.f;
#pragma unroll
    for (int j = 0; j < 32; j++) {
        v[j] = expf(v[j] - mx);
        sum += v[j];
    }
    float inv = 1.f / sum;
#pragma unroll
    for (int j = 0; j < 32; j++) g_attn[bh * 1024 + i * 32 + j] = v[j] * inv;
}

// ------------ M[b] = ao_w @ blockdiag(attn[b]), packed bf16 pairs ------------
__global__ void buildM_kernel(const float* __restrict__ ao_w) {
    int h = blockIdx.x, b = blockIdx.y;
    int tid = threadIdx.x;
    __shared__ float sa[32][33];
#pragma unroll
    for (int t = 0; t < 4; t++) {
        int idx = tid + t * 256;
        sa[idx >> 5][idx & 31] = g_attn[(b * HEADS_ + h) * 1024 + idx];
    }
    __syncthreads();
    float wreg[32];
#pragma unroll
    for (int c = 0; c < 32; c++) wreg[c] = ao_w[(size_t)tid * C_ + h * HD_ + c];
    float m[32];
#pragma unroll 4
    for (int d = 0; d < 32; d++) {
        float s = 0.f;
#pragma unroll
        for (int c = 0; c < 32; c++) s += wreg[c] * sa[c][d];
        m[d] = s;
    }
    unsigned* Mo = g_Mh + ((size_t)(b * C_) + tid) * 128 + h * 16;
#pragma unroll
    for (int j = 0; j < 16; j++) Mo[j] = packbf(m[2 * j], m[2 * j + 1]);
}

// ======= final GEMM: out = M@v + ao_b + pemb + hx (bf16 m16n8k16) ============
__global__ __launch_bounds__(256, 2) void gemm_outh_kernel(const float* __restrict__ bias,
                                                           const float* __restrict__ hx,
                                                           float* __restrict__ out) {
    __shared__ unsigned sm[2 * STG_U];
    int b = blockIdx.z;
    int oBase = blockIdx.x * 128;
    int pBase = blockIdx.y * 128;
    int tid = threadIdx.x;
    int wid = tid >> 5, lane = tid & 31;
    int g = lane >> 2, tig = lane & 3;
    int oW = (wid >> 2) * 64;
    int pW = (wid & 3) * 32;

    const unsigned* Mb = g_Mh + (size_t)b * C_ * 128;
    const bf16* Vb = g_v + (size_t)b * C_ * HW_;

    int lk2 = tid >> 4;
    int lp8 = (tid & 15) * 8;

    uint4 aR[2];
    uint4 vA, vB;
    auto ldg = [&](int kc) {
        int k0 = kc * 32;
#pragma unroll
        for (int i = 0; i < 2; i++) {
            int idx = tid + i * 256;
            int o = idx >> 2, q = idx & 3;
            aR[i] = *reinterpret_cast<const uint4*>(Mb + (size_t)(oBase + o) * 128 + k0 / 2 + q * 4);
        }
        int kk = k0 + 2 * lk2;
        vA = *reinterpret_cast<const uint4*>(Vb + (size_t)kk * HW_ + pBase + lp8);
        vB = *reinterpret_cast<const uint4*>(Vb + (size_t)(kk + 1) * HW_ + pBase + lp8);
    };
    auto sts = [&](int st) {
        unsigned* sA = sm + st * STG_U;
        unsigned* sB = sA + 128 * SA_U;
#pragma unroll
        for (int i = 0; i < 2; i++) {
            int idx = tid + i * 256;
            int o = idx >> 2, q = idx & 3;
            *reinterpret_cast<uint4*>(sA + o * SA_U + q * 4) = aR[i];
        }
        uint4 o0, o1;
        o0.x = __byte_perm(vA.x, vB.x, 0x5410);
        o0.y = __byte_perm(vA.x, vB.x, 0x7632);
        o0.z = __byte_perm(vA.y, vB.y, 0x5410);
        o0.w = __byte_perm(vA.y, vB.y, 0x7632);
        o1.x = __byte_perm(vA.z, vB.z, 0x5410);
        o1.y = __byte_perm(vA.z, vB.z, 0x7632);
        o1.z = __byte_perm(vA.w, vB.w, 0x5410);
        o1.w = __byte_perm(vA.w, vB.w, 0x7632);
        *reinterpret_cast<uint4*>(sB + lk2 * SB_U + lp8) = o0;
        *reinterpret_cast<uint4*>(sB + lk2 * SB_U + lp8 + 4) = o1;
    };

    float acc[4][4][4] = {};
    ldg(0);
    for (int kc = 0; kc < 8; kc++) {
        sts(kc & 1);
        __syncthreads();
        if (kc < 7) ldg(kc + 1);
        unsigned* sA = sm + (kc & 1) * STG_U;
        unsigned* sB = sA + 128 * SA_U;
#pragma unroll
        for (int s2 = 0; s2 < 16; s2 += 8) {
            unsigned afr[4][4];
#pragma unroll
            for (int mt = 0; mt < 4; mt++) {
                int ro = oW + mt * 16 + g;
                afr[mt][0] = sA[ro * SA_U + s2 + tig];
                afr[mt][1] = sA[(ro + 8) * SA_U + s2 + tig];
                afr[mt][2] = sA[ro * SA_U + s2 + 4 + tig];
                afr[mt][3] = sA[(ro + 8) * SA_U + s2 + 4 + tig];
            }
#pragma unroll
            for (int nt = 0; nt < 4; nt++) {
                int cp = pW + nt * 8 + g;
                unsigned b0 = sB[(s2 + tig) * SB_U + cp];
                unsigned b1 = sB[(s2 + 4 + tig) * SB_U + cp];
#pragma unroll
                for (int mt = 0; mt < 4; mt++)
                    mma_bf16(acc[mt][nt], afr[mt], b0, b1);
            }
        }
        __syncthreads();
    }

    const bf16* PEb = g_pe + (size_t)b * C_ * HW_;
    const float* HXb = hx + (size_t)b * C_ * HW_;
#pragma unroll
    for (int mt = 0; mt < 4; mt++) {
        int o0 = oBase + oW + mt * 16 + g;
        int o1 = o0 + 8;
        float b0v = bias[o0], b1v = bias[o1];
#pragma unroll
        for (int nt = 0; nt < 4; nt++) {
            int p = pBase + pW + nt * 8 + 2 * tig;
            float2 h0 = *reinterpret_cast<const float2*>(HXb + (size_t)o0 * HW_ + p);
            float2 h1 = *reinterpret_cast<const float2*>(HXb + (size_t)o1 * HW_ + p);
            float2 pf0 = __bfloat1622float2(
                *reinterpret_cast<const bf162*>(PEb + (size_t)o0 * HW_ + p));
            float2 pf1 = __bfloat1622float2(
                *reinterpret_cast<const bf162*>(PEb + (size_t)o1 * HW_ + p));
            float2 r0, r1;
            r0.x = acc[mt][nt][0] + b0v + pf0.x + h0.x;
            r0.y = acc[mt][nt][1] + b0v + pf0.y + h0.y;
            r1.x = acc[mt][nt][2] + b1v + pf1.x + h1.x;
            r1.y = acc[mt][nt][3] + b1v + pf1.y + h1.y;
            *reinterpret_cast<float2*>(out + ((size_t)b * C_ + o0) * HW_ + p) = r0;
            *reinterpret_cast<float2*>(out + ((size_t)b * C_ + o1) * HW_ + p) = r1;
        }
    }
}

// -----------------------------------------------------------------------------
extern "C" void kernel_launch(void* const* d_in, const int* in_sizes, int n_in,
                              void* d_out, int out_size) {
    const float* x = (const float*)d_in[0];
    const float* hx = (const float*)d_in[1];
    const float* ln1_w = (const float*)d_in[2];
    const float* ln1_b = (const float*)d_in[3];
    const float* ln2_w = (const float*)d_in[4];
    const float* ln2_b = (const float*)d_in[5];
    const float* q_w = (const float*)d_in[6];
    const float* q_b = (const float*)d_in[7];
    const float* q_dw_w = (const float*)d_in[8];
    const float* q_dw_b = (const float*)d_in[9];
    const float* kv_w = (const float*)d_in[10];
    const float* kv_b = (const float*)d_in[11];
    const float* kv_dw_w = (const float*)d_in[12];
    const float* kv_dw_b = (const float*)d_in[13];
    const float* ao_w = (const float*)d_in[14];
    const float* ao_b = (const float*)d_in[15];
    const float* pe1_w = (const float*)d_in[16];
    const float* pe2_w = (const float*)d_in[17];
    const float* temperature = (const float*)d_in[18];
    float* out = (float*)d_out;

    unsigned *p_Wqh, *p_Wkvh;
    float *p_bq, *p_bkv, *p_rsq, *p_rskv, *p_ss;
    bf16 *p_bufA, *p_bufB, *p_q, *p_k;
    cudaGetSymbolAddress((void**)&p_Wqh, g_Wqh);
    cudaGetSymbolAddress((void**)&p_Wkvh, g_Wkvh);
    cudaGetSymbolAddress((void**)&p_bq, g_bq);
    cudaGetSymbolAddress((void**)&p_bkv, g_bkv);
    cudaGetSymbolAddress((void**)&p_rsq, g_rsq);
    cudaGetSymbolAddress((void**)&p_rskv, g_rskv);
    cudaGetSymbolAddress((void**)&p_ss, g_ss);
    cudaGetSymbolAddress((void**)&p_bufA, g_bufA);
    cudaGetSymbolAddress((void**)&p_bufB, g_bufB);
    cudaGetSymbolAddress((void**)&p_q, g_q);
    cudaGetSymbolAddress((void**)&p_k, g_k);

    // 1. fold LN into weights (pack bf16 pairs); zero sumsq accumulators
    prep_w_kernel<<<3 * C_, 256>>>(q_w, q_b, ln1_w, ln1_b, kv_w, kv_b, ln2_w, ln2_b);

    // 2. q_pre = conv1x1(ln(x)) -> bufA ; kv_pre = conv1x1(ln(hx)) -> bufB
    {
        GemmArgs ga{};
        ga.X = x; ga.Wh = p_Wqh; ga.bias = p_bq; ga.rsum = p_rsq;
        ga.Yh = p_bufA; ga.O = C_;
        gemm_lnh_kernel<<<dim3(C_ / 128, HW_ / 128, B_), 256>>>(ga);
    }
    {
        GemmArgs ga{};
        ga.X = hx; ga.Wh = p_Wkvh; ga.bias = p_bkv; ga.rsum = p_rskv;
        ga.Yh = p_bufB; ga.O = 2 * C_;
        gemm_lnh_kernel<<<dim3(2 * C_ / 128, HW_ / 128, B_), 256>>>(ga);
    }

    // 3. q, k dwconvs (register-strip, no smem) -> g_q, g_k (+sumsq)
    dw_reg_kernel<<<dim3(1, C_, B_), 256>>>(p_bufA, C_, 0, q_dw_w, q_dw_b, p_q, p_ss);
    dw_reg_kernel<<<dim3(1, C_, B_), 256>>>(p_bufB, 2 * C_, 0, kv_dw_w, kv_dw_b, p_k,
                                            p_ss + B_ * C_);

    // 4. v dwconv + positional branch -> g_v, g_pe
    vpe_kernel<<<dim3(8, C_, B_), 256>>>(kv_dw_w, kv_dw_b, pe1_w, pe2_w);

    // 5. gram (bf16 mma, split-K=4), softmax with fused norms
    gram_mma<<<dim3(GSEG, HEADS_, B_), 256>>>();
    softmax_kernel<<<B_ * HEADS_, 32>>>(temperature);

    // 6. fold attn into output projection; final fused GEMM
    buildM_kernel<<<dim3(HEADS_, B_), 256>>>(ao_w);
    gemm_outh_kernel<<<dim3(C_ / 128, HW_ / 128, B_), 256>>>(ao_b, hx, out);
}

// round 9
// speedup vs baseline: 1.1857x; 1.0426x over previous
#include <cuda_runtime.h>
#include <cuda_bf16.h>
#include <math.h>
#include <stdint.h>

#define B_ 8
#define C_ 256
#define H_ 128
#define W_ 128
#define HW_ 16384
#define HEADS_ 8
#define HD_ 32
#define GSEG 4

typedef __nv_bfloat16 bf16;
typedef __nv_bfloat162 bf162;

// ---------------- scratch (device globals; no allocation allowed) ------------
__device__ bf16 g_bufA[B_ * C_ * HW_];           // q_pre
__device__ bf16 g_bufB[B_ * 2 * C_ * HW_];       // kv_pre
__device__ bf16 g_q[B_ * C_ * HW_];
__device__ bf16 g_k[B_ * C_ * HW_];
__device__ bf16 g_v[B_ * C_ * HW_];
__device__ bf16 g_pe[B_ * C_ * HW_];             // pemb (WITHOUT hx)
__device__ unsigned g_Wqh[C_ * 128];             // bf16-pair packed folded weights
__device__ unsigned g_Wkvh[2 * C_ * 128];
__device__ unsigned g_Mh[B_ * C_ * 128];         // packed M = ao_w @ blockdiag(attn)
__device__ float g_bq[C_];
__device__ float g_bkv[2 * C_];
__device__ float g_rsq[C_];
__device__ float g_rskv[2 * C_];
__device__ float g_ss[2 * B_ * C_];
__device__ float g_part[B_ * HEADS_ * GSEG * 1024];
__device__ float g_attn[B_ * HEADS_ * 1024];

// ---------------- helpers ------------------------------------------------
__device__ __forceinline__ void mma_bf16(float* c, const unsigned* a, unsigned b0, unsigned b1) {
    asm volatile(
        "mma.sync.aligned.m16n8k16.row.col.f32.bf16.bf16.f32 "
        "{%0,%1,%2,%3}, {%4,%5,%6,%7}, {%8,%9}, {%0,%1,%2,%3};\n"
        : "+f"(c[0]), "+f"(c[1]), "+f"(c[2]), "+f"(c[3])
        : "r"(a[0]), "r"(a[1]), "r"(a[2]), "r"(a[3]), "r"(b0), "r"(b1));
}
__device__ __forceinline__ unsigned packbf(float lo, float hi) {
    bf162 t = __floats2bfloat162_rn(lo, hi);
    return *reinterpret_cast<unsigned*>(&t);
}
__device__ __forceinline__ float gelu_tanh(float s) {
    float x3 = s * s * s;
    return 0.5f * s * (1.f + tanhf(0.7978845608028654f * (s + 0.044715f * x3)));
}
__device__ __forceinline__ void u4_to_f8(uint4 u, float4& lo, float4& hi) {
    bf162 h0 = *reinterpret_cast<bf162*>(&u.x);
    bf162 h1 = *reinterpret_cast<bf162*>(&u.y);
    bf162 h2 = *reinterpret_cast<bf162*>(&u.z);
    bf162 h3 = *reinterpret_cast<bf162*>(&u.w);
    float2 f0 = __bfloat1622float2(h0), f1 = __bfloat1622float2(h1);
    float2 f2 = __bfloat1622float2(h2), f3 = __bfloat1622float2(h3);
    lo = make_float4(f0.x, f0.y, f1.x, f1.y);
    hi = make_float4(f2.x, f2.y, f3.x, f3.y);
}
__device__ __forceinline__ uint4 f8_to_u4(const float* o) {
    uint4 r;
    r.x = packbf(o[0], o[1]);
    r.y = packbf(o[2], o[3]);
    r.z = packbf(o[4], o[5]);
    r.w = packbf(o[6], o[7]);
    return r;
}

// 8-wide 3-tap over a padded smem row (data at +4; pads zero at 0..3 / 132..135)
__device__ __forceinline__ void stencil8(const float* R, int s, float w0, float w1, float w2,
                                         float* o) {
    float4 m0 = *reinterpret_cast<const float4*>(R + 4 + s);
    float4 m1 = *reinterpret_cast<const float4*>(R + 8 + s);
    float l = R[3 + s], r = R[12 + s];
    o[0] += w0 * l    + w1 * m0.x + w2 * m0.y;
    o[1] += w0 * m0.x + w1 * m0.y + w2 * m0.z;
    o[2] += w0 * m0.y + w1 * m0.z + w2 * m0.w;
    o[3] += w0 * m0.z + w1 * m0.w + w2 * m1.x;
    o[4] += w0 * m0.w + w1 * m1.x + w2 * m1.y;
    o[5] += w0 * m1.x + w1 * m1.y + w2 * m1.z;
    o[6] += w0 * m1.y + w1 * m1.z + w2 * m1.w;
    o[7] += w0 * m1.z + w1 * m1.w + w2 * r;
}

// single-pass fill of N padded rows from bf16 global (row gr = r0+roff+row; OOB -> zeros)
template <int NROWS>
__device__ __forceinline__ void fill_rows(float (*dst)[136], const bf16* src, int r0, int roff,
                                          int tid) {
    float4 z4 = make_float4(0.f, 0.f, 0.f, 0.f);
    for (int i = tid; i < NROWS * 16; i += 256) {
        int row = i >> 4, c8 = (i & 15) * 8;
        int gr = r0 + roff + row;
        float4 lo = z4, hi = z4;
        if (gr >= 0 && gr < H_) {
            uint4 u = *reinterpret_cast<const uint4*>(src + (size_t)gr * W_ + c8);
            u4_to_f8(u, lo, hi);
        }
        *reinterpret_cast<float4*>(&dst[row][4 + c8]) = lo;
        *reinterpret_cast<float4*>(&dst[row][8 + c8]) = hi;
    }
    for (int i = tid; i < NROWS * 2; i += 256) {
        int row = i >> 1;
        *reinterpret_cast<float4*>(&dst[row][(i & 1) ? 132 : 0]) = z4;
    }
}

// ---------------- weight prep: fold LN gamma/beta, pack to bf16 pairs --------
__global__ void prep_w_kernel(const float* __restrict__ qw, const float* __restrict__ qb,
                              const float* __restrict__ ln1w, const float* __restrict__ ln1b,
                              const float* __restrict__ kvw, const float* __restrict__ kvb,
                              const float* __restrict__ ln2w, const float* __restrict__ ln2b) {
    int r = blockIdx.x;
    int tid = threadIdx.x;
    if (r < 16) g_ss[r * 256 + tid] = 0.f;
    const float *w, *lnw, *lnb;
    float cb;
    unsigned* dWh;
    float *dB, *dR;
    if (r < C_) {
        int o = r;
        w = qw + (size_t)o * C_; lnw = ln1w; lnb = ln1b; cb = qb[o];
        dWh = g_Wqh + (size_t)o * 128; dB = g_bq + o; dR = g_rsq + o;
    } else {
        int o = r - C_;
        w = kvw + (size_t)o * C_; lnw = ln2w; lnb = ln2b; cb = kvb[o];
        dWh = g_Wkvh + (size_t)o * 128; dB = g_bkv + o; dR = g_rskv + o;
    }
    float wv = w[tid];
    float we = wv * lnw[tid];
    float we_r = __bfloat162float(__float2bfloat16(we));
    __shared__ float shw[256], sh1[256], sh2[256];
    shw[tid] = we_r;
    sh1[tid] = we_r;
    sh2[tid] = wv * lnb[tid];
    __syncthreads();
    if (tid < 128) dWh[tid] = packbf(shw[2 * tid], shw[2 * tid + 1]);
    for (int s = 128; s > 0; s >>= 1) {
        if (tid < s) { sh1[tid] += sh1[tid + s]; sh2[tid] += sh2[tid + s]; }
        __syncthreads();
    }
    if (tid == 0) { *dR = sh1[0]; *dB = cb + sh2[0]; }
}

// ========= LN-fused GEMM: bf16 m16n8k16, fp32 X -> bf16 pack on the fly ======
struct GemmArgs {
    const float* X;
    const unsigned* Wh;
    const float* bias;
    const float* rsum;
    bf16* Yh;
    int O;
};

#define SA_U 20
#define SB_U 136
#define STG_U (128 * SA_U + 16 * SB_U)   // 4736 uints / stage

__global__ __launch_bounds__(256, 2) void gemm_lnh_kernel(GemmArgs ga) {
    __shared__ unsigned sm[2 * STG_U];
    __shared__ float sS[8][128], sQ[8][128];
    int b = blockIdx.z;
    int oBase = blockIdx.x * 128;
    int pBase = blockIdx.y * 128;
    int tid = threadIdx.x;
    int wid = tid >> 5, lane = tid & 31;
    int g = lane >> 2, tig = lane & 3;
    int oW = (wid >> 2) * 64;
    int pW = (wid & 3) * 32;

    const float* Xb = ga.X + (size_t)b * C_ * HW_;
    const unsigned* Wb = ga.Wh;

    int lk2 = tid >> 5;
    int lp0 = (tid & 31) * 4;

    uint4 wR[2];
    float4 xR[2][2];
    auto ldg = [&](int kc) {
        int k0 = kc * 32;
#pragma unroll
        for (int i = 0; i < 2; i++) {
            int idx = tid + i * 256;
            int o = idx >> 2, q = idx & 3;
            wR[i] = *reinterpret_cast<const uint4*>(Wb + (size_t)(oBase + o) * 128 + k0 / 2 + q * 4);
        }
#pragma unroll
        for (int i = 0; i < 2; i++) {
            int kk = k0 + 2 * (lk2 + i * 8);
            xR[i][0] = *reinterpret_cast<const float4*>(Xb + (size_t)kk * HW_ + pBase + lp0);
            xR[i][1] = *reinterpret_cast<const float4*>(Xb + (size_t)(kk + 1) * HW_ + pBase + lp0);
        }
    };
    float stS[4] = {}, stQ[4] = {};
    auto sts = [&](int st) {
        unsigned* sA = sm + st * STG_U;
        unsigned* sB = sA + 128 * SA_U;
#pragma unroll
        for (int i = 0; i < 2; i++) {
            int idx = tid + i * 256;
            int o = idx >> 2, q = idx & 3;
            *reinterpret_cast<uint4*>(sA + o * SA_U + q * 4) = wR[i];
        }
#pragma unroll
        for (int i = 0; i < 2; i++) {
            float4 a = xR[i][0], c = xR[i][1];
            stS[0] += a.x + c.x; stQ[0] += a.x * a.x + c.x * c.x;
            stS[1] += a.y + c.y; stQ[1] += a.y * a.y + c.y * c.y;
            stS[2] += a.z + c.z; stQ[2] += a.z * a.z + c.z * c.z;
            stS[3] += a.w + c.w; stQ[3] += a.w * a.w + c.w * c.w;
            uint4 u;
            u.x = packbf(a.x, c.x);
            u.y = packbf(a.y, c.y);
            u.z = packbf(a.z, c.z);
            u.w = packbf(a.w, c.w);
            *reinterpret_cast<uint4*>(sB + (lk2 + i * 8) * SB_U + lp0) = u;
        }
    };

    float acc[4][4][4] = {};
    ldg(0);
    for (int kc = 0; kc < 8; kc++) {
        sts(kc & 1);
        __syncthreads();
        if (kc < 7) ldg(kc + 1);
        unsigned* sA = sm + (kc & 1) * STG_U;
        unsigned* sB = sA + 128 * SA_U;
#pragma unroll
        for (int s2 = 0; s2 < 16; s2 += 8) {
            unsigned afr[4][4];
#pragma unroll
            for (int mt = 0; mt < 4; mt++) {
                int ro = oW + mt * 16 + g;
                afr[mt][0] = sA[ro * SA_U + s2 + tig];
                afr[mt][1] = sA[(ro + 8) * SA_U + s2 + tig];
                afr[mt][2] = sA[ro * SA_U + s2 + 4 + tig];
                afr[mt][3] = sA[(ro + 8) * SA_U + s2 + 4 + tig];
            }
#pragma unroll
            for (int nt = 0; nt < 4; nt++) {
                int cp = pW + nt * 8 + g;
                unsigned b0 = sB[(s2 + tig) * SB_U + cp];
                unsigned b1 = sB[(s2 + 4 + tig) * SB_U + cp];
#pragma unroll
                for (int mt = 0; mt < 4; mt++)
                    mma_bf16(acc[mt][nt], afr[mt], b0, b1);
            }
        }
        __syncthreads();
    }

    *reinterpret_cast<float4*>(&sS[lk2][lp0]) = make_float4(stS[0], stS[1], stS[2], stS[3]);
    *reinterpret_cast<float4*>(&sQ[lk2][lp0]) = make_float4(stQ[0], stQ[1], stQ[2], stQ[3]);
    __syncthreads();
    float mu[4][2], iv[4][2];
#pragma unroll
    for (int nt = 0; nt < 4; nt++) {
#pragma unroll
        for (int u = 0; u < 2; u++) {
            int pl = pW + nt * 8 + 2 * tig + u;
            float s0 = 0.f, q0 = 0.f;
#pragma unroll
            for (int wrow = 0; wrow < 8; wrow++) { s0 += sS[wrow][pl]; q0 += sQ[wrow][pl]; }
            float m = s0 * (1.f / 256.f);
            float var = q0 * (1.f / 256.f) - m * m;
            mu[nt][u] = m;
            iv[nt][u] = rsqrtf(var + 1e-5f);
        }
    }
#pragma unroll
    for (int mt = 0; mt < 4; mt++) {
        int o0 = oBase + oW + mt * 16 + g;
        int o1 = o0 + 8;
        float rs0 = ga.rsum[o0], b0v = ga.bias[o0];
        float rs1 = ga.rsum[o1], b1v = ga.bias[o1];
#pragma unroll
        for (int nt = 0; nt < 4; nt++) {
            int p = pBase + pW + nt * 8 + 2 * tig;
            bf162 r0 = __floats2bfloat162_rn(
                iv[nt][0] * (acc[mt][nt][0] - mu[nt][0] * rs0) + b0v,
                iv[nt][1] * (acc[mt][nt][1] - mu[nt][1] * rs0) + b0v);
            bf162 r1 = __floats2bfloat162_rn(
                iv[nt][0] * (acc[mt][nt][2] - mu[nt][0] * rs1) + b1v,
                iv[nt][1] * (acc[mt][nt][3] - mu[nt][1] * rs1) + b1v);
            *reinterpret_cast<bf162*>(ga.Yh + ((size_t)b * ga.O + o0) * HW_ + p) = r0;
            *reinterpret_cast<bf162*>(ga.Yh + ((size_t)b * ga.O + o1) * HW_ + p) = r1;
        }
    }
}

// ===== merged q+k register-strip depthwise 3x3 (+bias, +sumsq), no smem =======
// thread: 4x8 output patch; streams 6 input rows through registers.
// grid: (2, 2*C, B). ci<C -> q path (bufA), else k path (bufB first half).
__global__ __launch_bounds__(256, 4) void dwqk_kernel(const float* __restrict__ qw9,
                                                      const float* __restrict__ qb,
                                                      const float* __restrict__ kvw9,
                                                      const float* __restrict__ kvb) {
    int b = blockIdx.z, ci = blockIdx.y;
    int tid = threadIdx.x;
    int cg = tid & 15, rg = tid >> 4;
    int c0 = cg * 8, r0 = blockIdx.x * 64 + rg * 4;

    const bf16* Xc;
    const float* w9;
    const float* bp;
    bf16* D;
    float* ssq;
    if (ci < C_) {
        Xc = g_bufA + ((size_t)(b * C_ + ci)) * HW_;
        w9 = qw9 + (size_t)ci * 9;
        bp = qb + ci;
        D = g_q + ((size_t)(b * C_ + ci)) * HW_;
        ssq = &g_ss[b * C_ + ci];
    } else {
        int c = ci - C_;
        Xc = g_bufB + ((size_t)(b * 2 * C_ + c)) * HW_;
        w9 = kvw9 + (size_t)c * 9;
        bp = kvb + c;
        D = g_k + ((size_t)(b * C_ + c)) * HW_;
        ssq = &g_ss[B_ * C_ + b * C_ + c];
    }
    float wk[9];
#pragma unroll
    for (int t = 0; t < 9; t++) wk[t] = __ldg(w9 + t);
    float bv = __ldg(bp);

    float acc[4][8];
#pragma unroll
    for (int r = 0; r < 4; r++)
#pragma unroll
        for (int u = 0; u < 8; u++) acc[r][u] = bv;
#pragma unroll
    for (int t = 0; t < 6; t++) {
        int ir = r0 - 1 + t;
        float f[10];
#pragma unroll
        for (int u = 0; u < 10; u++) f[u] = 0.f;
        if (ir >= 0 && ir < H_) {
            uint4 u4 = *reinterpret_cast<const uint4*>(Xc + (size_t)ir * W_ + c0);
            float4 lo, hi;
            u4_to_f8(u4, lo, hi);
            f[1] = lo.x; f[2] = lo.y; f[3] = lo.z; f[4] = lo.w;
            f[5] = hi.x; f[6] = hi.y; f[7] = hi.z; f[8] = hi.w;
            if (c0 > 0) f[0] = __bfloat162float(__ldg(Xc + (size_t)ir * W_ + c0 - 1));
            if (c0 + 8 < W_) f[9] = __bfloat162float(__ldg(Xc + (size_t)ir * W_ + c0 + 8));
        }
        if (t >= 2) {
#pragma unroll
            for (int u = 0; u < 8; u++)
                acc[t - 2][u] += wk[6] * f[u] + wk[7] * f[u + 1] + wk[8] * f[u + 2];
        }
        if (t >= 1 && t <= 4) {
#pragma unroll
            for (int u = 0; u < 8; u++)
                acc[t - 1][u] += wk[3] * f[u] + wk[4] * f[u + 1] + wk[5] * f[u + 2];
        }
        if (t <= 3) {
#pragma unroll
            for (int u = 0; u < 8; u++)
                acc[t][u] += wk[0] * f[u] + wk[1] * f[u + 1] + wk[2] * f[u + 2];
        }
    }
    float ss = 0.f;
#pragma unroll
    for (int r = 0; r < 4; r++) {
        *reinterpret_cast<uint4*>(D + (size_t)(r0 + r) * W_ + c0) = f8_to_u4(acc[r]);
#pragma unroll
        for (int u = 0; u < 8; u++) ss += acc[r][u] * acc[r][u];
    }
#pragma unroll
    for (int d = 16; d > 0; d >>= 1) ss += __shfl_down_sync(0xffffffffu, ss, d);
    if ((tid & 31) == 0) atomicAdd(ssq, ss);
}

// ------------- v dwconv + positional branch (k handled by dwqk) ---------------
__global__ __launch_bounds__(256) void vpe_kernel(const float* __restrict__ kvw9,
                                                  const float* __restrict__ kvb,
                                                  const float* __restrict__ pe1,
                                                  const float* __restrict__ pe2) {
    __shared__ float sbuf[(22 + 20) * 136];
    float (*svi)[136] = reinterpret_cast<float(*)[136]>(sbuf);            // 22 rows
    float (*sv)[136]  = reinterpret_cast<float(*)[136]>(sbuf + 22 * 136); // 20 rows
    float (*st1)[136] = svi;                                              // alias (18 rows)
    int b = blockIdx.z, c = blockIdx.y, r0 = blockIdx.x * 16;
    int tid = threadIdx.x;
    const bf16* Vc = g_bufB + ((size_t)(b * 2 * C_ + C_ + c)) * HW_;
    fill_rows<22>(svi, Vc, r0, -3, tid);
    {
        float4 z4 = make_float4(0.f, 0.f, 0.f, 0.f);
        for (int i = tid; i < 20 * 2; i += 256)
            *reinterpret_cast<float4*>(&sv[i >> 1][(i & 1) ? 132 : 0]) = z4;
    }
    float wkv[9], w1[9], w2[9];
#pragma unroll
    for (int t = 0; t < 9; t++) {
        wkv[t] = __ldg(kvw9 + (size_t)(C_ + c) * 9 + t);
        w1[t] = __ldg(pe1 + (size_t)c * 9 + t);
        w2[t] = __ldg(pe2 + (size_t)c * 9 + t);
    }
    float bvv = __ldg(kvb + C_ + c);
    __syncthreads();

    int row0 = tid >> 4, s0 = (tid & 15) * 8;

    bf16* Dv = g_v + ((size_t)(b * C_ + c)) * HW_;
    for (int i = tid; i < 20 * 16; i += 256) {
        int row = i >> 4, cc = (i & 15) * 8;
        int gr = r0 - 2 + row;
        float o[8] = {};
        if (gr >= 0 && gr < H_) {
#pragma unroll
            for (int u = 0; u < 8; u++) o[u] = bvv;
#pragma unroll
            for (int dr = 0; dr < 3; dr++)
                stencil8(svi[row + dr], cc, wkv[dr * 3], wkv[dr * 3 + 1], wkv[dr * 3 + 2], o);
        }
        *reinterpret_cast<float4*>(&sv[row][4 + cc]) = make_float4(o[0], o[1], o[2], o[3]);
        *reinterpret_cast<float4*>(&sv[row][8 + cc]) = make_float4(o[4], o[5], o[6], o[7]);
        if (row >= 2 && row < 18)
            *reinterpret_cast<uint4*>(Dv + (size_t)gr * W_ + cc) = f8_to_u4(o);
    }
    __syncthreads();

    for (int i = tid; i < 18 * 16; i += 256) {
        int row = i >> 4, cc = (i & 15) * 8;
        int gr = r0 - 1 + row;
        float o[8] = {};
        if (gr >= 0 && gr < H_) {
#pragma unroll
            for (int dr = 0; dr < 3; dr++)
                stencil8(sv[row + dr], cc, w1[dr * 3], w1[dr * 3 + 1], w1[dr * 3 + 2], o);
#pragma unroll
            for (int u = 0; u < 8; u++) o[u] = gelu_tanh(o[u]);
        }
        *reinterpret_cast<float4*>(&st1[row][4 + cc]) = make_float4(o[0], o[1], o[2], o[3]);
        *reinterpret_cast<float4*>(&st1[row][8 + cc]) = make_float4(o[4], o[5], o[6], o[7]);
    }
    __syncthreads();

    bf16* Dp = g_pe + ((size_t)(b * C_ + c)) * HW_;
    {
        float o[8] = {};
#pragma unroll
        for (int dr = 0; dr < 3; dr++)
            stencil8(st1[row0 + dr], s0, w2[dr * 3], w2[dr * 3 + 1], w2[dr * 3 + 2], o);
        *reinterpret_cast<uint4*>(Dp + (size_t)(r0 + row0) * W_ + s0) = f8_to_u4(o);
    }
}

// ---------------- gram via bf16 mma m16n8k16, split-K=4 ----------------------
__global__ __launch_bounds__(256) void gram_mma() {
    __shared__ float sbuf[8192];
    bf16* sqh = reinterpret_cast<bf16*>(sbuf);
    bf16* skh = sqh + 32 * 136;
    unsigned* squ = reinterpret_cast<unsigned*>(sqh);
    unsigned* sku = reinterpret_cast<unsigned*>(skh);
    int seg = blockIdx.x, h = blockIdx.y, b = blockIdx.z;
    const bf16* Q = g_q + ((size_t)(b * C_ + h * HD_)) * HW_;
    const bf16* K = g_k + ((size_t)(b * C_ + h * HD_)) * HW_;
    int tid = threadIdx.x, wid = tid >> 5, lane = tid & 31;
    int g = lane >> 2, tig = lane & 3;
    float acc[2][4][4] = {};
    int n0 = seg * (HW_ / GSEG);
    int klu = wid * 8;
    for (int ch = 0; ch < (HW_ / GSEG) / 128; ch++) {
        int base = n0 + ch * 128;
        for (int i = tid; i < 32 * 16; i += 256) {
            int row = i >> 4, c8 = (i & 15) * 8;
            *reinterpret_cast<uint4*>(sqh + row * 136 + c8) =
                *reinterpret_cast<const uint4*>(Q + (size_t)row * HW_ + base + c8);
            *reinterpret_cast<uint4*>(skh + row * 136 + c8) =
                *reinterpret_cast<const uint4*>(K + (size_t)row * HW_ + base + c8);
        }
        __syncthreads();
        unsigned afr[2][4];
#pragma unroll
        for (int mt = 0; mt < 2; mt++) {
            int r = mt * 16 + g;
            afr[mt][0] = squ[r * 68 + klu + tig];
            afr[mt][1] = squ[(r + 8) * 68 + klu + tig];
            afr[mt][2] = squ[r * 68 + klu + 4 + tig];
            afr[mt][3] = squ[(r + 8) * 68 + klu + 4 + tig];
        }
#pragma unroll
        for (int nt = 0; nt < 4; nt++) {
            unsigned b0 = sku[(nt * 8 + g) * 68 + klu + tig];
            unsigned b1 = sku[(nt * 8 + g) * 68 + klu + 4 + tig];
#pragma unroll
            for (int mt = 0; mt < 2; mt++)
                mma_bf16(acc[mt][nt], afr[mt], b0, b1);
        }
        __syncthreads();
    }
    float* red = sbuf;
#pragma unroll
    for (int mt = 0; mt < 2; mt++)
#pragma unroll
        for (int nt = 0; nt < 4; nt++) {
            int r = mt * 16 + g, cl = nt * 8 + 2 * tig;
            red[wid * 1024 + r * 32 + cl] = acc[mt][nt][0];
            red[wid * 1024 + r * 32 + cl + 1] = acc[mt][nt][1];
            red[wid * 1024 + (r + 8) * 32 + cl] = acc[mt][nt][2];
            red[wid * 1024 + (r + 8) * 32 + cl + 1] = acc[mt][nt][3];
        }
    __syncthreads();
    float* outp = g_part + ((size_t)(b * HEADS_ + h) * GSEG + seg) * 1024;
    for (int i = tid; i < 1024; i += 256) {
        float s = 0.f;
#pragma unroll
        for (int w = 0; w < 8; w++) s += red[w * 1024 + i];
        outp[i] = s;
    }
}

// ---------------- softmax with fused q/k norm scales + temperature -----------
__global__ void softmax_kernel(const float* __restrict__ temp) {
    int bh = blockIdx.x;
    int b = bh >> 3, h = bh & 7;
    int i = threadIdx.x;
    float qs = 1.f / fmaxf(sqrtf(g_ss[b * C_ + h * HD_ + i]), 1e-12f);
    float T = __ldg(temp + h);
    float v[32];
    float mx = -1e30f;
#pragma unroll 4
    for (int j = 0; j < 32; j++) {
        float s = 0.f;
#pragma unroll
        for (int seg = 0; seg < GSEG; seg++)
            s += g_part[((size_t)bh * GSEG + seg) * 1024 + i * 32 + j];
        float ks = 1.f / fmaxf(sqrtf(g_ss[B_ * C_ + b * C_ + h * HD_ + j]), 1e-12f);
        float val = s * qs * ks * T;
        v[j] = val;
        mx = fmaxf(mx, val);
    }
    float sum = 0.f;
#pragma unroll
    for (int j = 0; j < 32; j++) {
        v[j] = expf(v[j] - mx);
        sum += v[j];
    }
    float inv = 1.f / sum;
#pragma unroll
    for (int j = 0; j < 32; j++) g_attn[bh * 1024 + i * 32 + j] = v[j] * inv;
}

// ------------ M[b] = ao_w @ blockdiag(attn[b]), packed bf16 pairs ------------
__global__ void buildM_kernel(const float* __restrict__ ao_w) {
    int h = blockIdx.x, b = blockIdx.y;
    int tid = threadIdx.x;
    __shared__ float sa[32][33];
#pragma unroll
    for (int t = 0; t < 4; t++) {
        int idx = tid + t * 256;
        sa[idx >> 5][idx & 31] = g_attn[(b * HEADS_ + h) * 1024 + idx];
    }
    __syncthreads();
    float wreg[32];
#pragma unroll
    for (int c = 0; c < 32; c++) wreg[c] = ao_w[(size_t)tid * C_ + h * HD_ + c];
    float m[32];
#pragma unroll 4
    for (int d = 0; d < 32; d++) {
        float s = 0.f;
#pragma unroll
        for (int c = 0; c < 32; c++) s += wreg[c] * sa[c][d];
        m[d] = s;
    }
    unsigned* Mo = g_Mh + ((size_t)(b * C_) + tid) * 128 + h * 16;
#pragma unroll
    for (int j = 0; j < 16; j++) Mo[j] = packbf(m[2 * j], m[2 * j + 1]);
}

// ======= final GEMM: out = M@v + ao_b + pemb + hx (bf16 m16n8k16) ============
__global__ __launch_bounds__(256, 2) void gemm_outh_kernel(const float* __restrict__ bias,
                                                           const float* __restrict__ hx,
                                                           float* __restrict__ out) {
    __shared__ unsigned sm[2 * STG_U];
    int b = blockIdx.z;
    int oBase = blockIdx.x * 128;
    int pBase = blockIdx.y * 128;
    int tid = threadIdx.x;
    int wid = tid >> 5, lane = tid & 31;
    int g = lane >> 2, tig = lane & 3;
    int oW = (wid >> 2) * 64;
    int pW = (wid & 3) * 32;

    const unsigned* Mb = g_Mh + (size_t)b * C_ * 128;
    const bf16* Vb = g_v + (size_t)b * C_ * HW_;

    int lk2 = tid >> 4;
    int lp8 = (tid & 15) * 8;

    uint4 aR[2];
    uint4 vA, vB;
    auto ldg = [&](int kc) {
        int k0 = kc * 32;
#pragma unroll
        for (int i = 0; i < 2; i++) {
            int idx = tid + i * 256;
            int o = idx >> 2, q = idx & 3;
            aR[i] = *reinterpret_cast<const uint4*>(Mb + (size_t)(oBase + o) * 128 + k0 / 2 + q * 4);
        }
        int kk = k0 + 2 * lk2;
        vA = *reinterpret_cast<const uint4*>(Vb + (size_t)kk * HW_ + pBase + lp8);
        vB = *reinterpret_cast<const uint4*>(Vb + (size_t)(kk + 1) * HW_ + pBase + lp8);
    };
    auto sts = [&](int st) {
        unsigned* sA = sm + st * STG_U;
        unsigned* sB = sA + 128 * SA_U;
#pragma unroll
        for (int i = 0; i < 2; i++) {
            int idx = tid + i * 256;
            int o = idx >> 2, q = idx & 3;
            *reinterpret_cast<uint4*>(sA + o * SA_U + q * 4) = aR[i];
        }
        uint4 o0, o1;
        o0.x = __byte_perm(vA.x, vB.x, 0x5410);
        o0.y = __byte_perm(vA.x, vB.x, 0x7632);
        o0.z = __byte_perm(vA.y, vB.y, 0x5410);
        o0.w = __byte_perm(vA.y, vB.y, 0x7632);
        o1.x = __byte_perm(vA.z, vB.z, 0x5410);
        o1.y = __byte_perm(vA.z, vB.z, 0x7632);
        o1.z = __byte_perm(vA.w, vB.w, 0x5410);
        o1.w = __byte_perm(vA.w, vB.w, 0x7632);
        *reinterpret_cast<uint4*>(sB + lk2 * SB_U + lp8) = o0;
        *reinterpret_cast<uint4*>(sB + lk2 * SB_U + lp8 + 4) = o1;
    };

    float acc[4][4][4] = {};
    ldg(0);
    for (int kc = 0; kc < 8; kc++) {
        sts(kc & 1);
        __syncthreads();
        if (kc < 7) ldg(kc + 1);
        unsigned* sA = sm + (kc & 1) * STG_U;
        unsigned* sB = sA + 128 * SA_U;
#pragma unroll
        for (int s2 = 0; s2 < 16; s2 += 8) {
            unsigned afr[4][4];
#pragma unroll
            for (int mt = 0; mt < 4; mt++) {
                int ro = oW + mt * 16 + g;
                afr[mt][0] = sA[ro * SA_U + s2 + tig];
                afr[mt][1] = sA[(ro + 8) * SA_U + s2 + tig];
                afr[mt][2] = sA[ro * SA_U + s2 + 4 + tig];
                afr[mt][3] = sA[(ro + 8) * SA_U + s2 + 4 + tig];
            }
#pragma unroll
            for (int nt = 0; nt < 4; nt++) {
                int cp = pW + nt * 8 + g;
                unsigned b0 = sB[(s2 + tig) * SB_U + cp];
                unsigned b1 = sB[(s2 + 4 + tig) * SB_U + cp];
#pragma unroll
                for (int mt = 0; mt < 4; mt++)
                    mma_bf16(acc[mt][nt], afr[mt], b0, b1);
            }
        }
        __syncthreads();
    }

    const bf16* PEb = g_pe + (size_t)b * C_ * HW_;
    const float* HXb = hx + (size_t)b * C_ * HW_;
#pragma unroll
    for (int mt = 0; mt < 4; mt++) {
        int o0 = oBase + oW + mt * 16 + g;
        int o1 = o0 + 8;
        float b0v = bias[o0], b1v = bias[o1];
#pragma unroll
        for (int nt = 0; nt < 4; nt++) {
            int p = pBase + pW + nt * 8 + 2 * tig;
            float2 h0 = *reinterpret_cast<const float2*>(HXb + (size_t)o0 * HW_ + p);
            float2 h1 = *reinterpret_cast<const float2*>(HXb + (size_t)o1 * HW_ + p);
            float2 pf0 = __bfloat1622float2(
                *reinterpret_cast<const bf162*>(PEb + (size_t)o0 * HW_ + p));
            float2 pf1 = __bfloat1622float2(
                *reinterpret_cast<const bf162*>(PEb + (size_t)o1 * HW_ + p));
            float2 r0, r1;
            r0.x = acc[mt][nt][0] + b0v + pf0.x + h0.x;
            r0.y = acc[mt][nt][1] + b0v + pf0.y + h0.y;
            r1.x = acc[mt][nt][2] + b1v + pf1.x + h1.x;
            r1.y = acc[mt][nt][3] + b1v + pf1.y + h1.y;
            *reinterpret_cast<float2*>(out + ((size_t)b * C_ + o0) * HW_ + p) = r0;
            *reinterpret_cast<float2*>(out + ((size_t)b * C_ + o1) * HW_ + p) = r1;
        }
    }
}

// -----------------------------------------------------------------------------
extern "C" void kernel_launch(void* const* d_in, const int* in_sizes, int n_in,
                              void* d_out, int out_size) {
    const float* x = (const float*)d_in[0];
    const float* hx = (const float*)d_in[1];
    const float* ln1_w = (const float*)d_in[2];
    const float* ln1_b = (const float*)d_in[3];
    const float* ln2_w = (const float*)d_in[4];
    const float* ln2_b = (const float*)d_in[5];
    const float* q_w = (const float*)d_in[6];
    const float* q_b = (const float*)d_in[7];
    const float* q_dw_w = (const float*)d_in[8];
    const float* q_dw_b = (const float*)d_in[9];
    const float* kv_w = (const float*)d_in[10];
    const float* kv_b = (const float*)d_in[11];
    const float* kv_dw_w = (const float*)d_in[12];
    const float* kv_dw_b = (const float*)d_in[13];
    const float* ao_w = (const float*)d_in[14];
    const float* ao_b = (const float*)d_in[15];
    const float* pe1_w = (const float*)d_in[16];
    const float* pe2_w = (const float*)d_in[17];
    const float* temperature = (const float*)d_in[18];
    float* out = (float*)d_out;

    unsigned *p_Wqh, *p_Wkvh;
    float *p_bq, *p_bkv, *p_rsq, *p_rskv;
    bf16 *p_bufA, *p_bufB;
    cudaGetSymbolAddress((void**)&p_Wqh, g_Wqh);
    cudaGetSymbolAddress((void**)&p_Wkvh, g_Wkvh);
    cudaGetSymbolAddress((void**)&p_bq, g_bq);
    cudaGetSymbolAddress((void**)&p_bkv, g_bkv);
    cudaGetSymbolAddress((void**)&p_rsq, g_rsq);
    cudaGetSymbolAddress((void**)&p_rskv, g_rskv);
    cudaGetSymbolAddress((void**)&p_bufA, g_bufA);
    cudaGetSymbolAddress((void**)&p_bufB, g_bufB);

    // 1. fold LN into weights (pack bf16 pairs); zero sumsq accumulators
    prep_w_kernel<<<3 * C_, 256>>>(q_w, q_b, ln1_w, ln1_b, kv_w, kv_b, ln2_w, ln2_b);

    // 2. q_pre = conv1x1(ln(x)) -> bufA ; kv_pre = conv1x1(ln(hx)) -> bufB
    {
        GemmArgs ga{};
        ga.X = x; ga.Wh = p_Wqh; ga.bias = p_bq; ga.rsum = p_rsq;
        ga.Yh = p_bufA; ga.O = C_;
        gemm_lnh_kernel<<<dim3(C_ / 128, HW_ / 128, B_), 256>>>(ga);
    }
    {
        GemmArgs ga{};
        ga.X = hx; ga.Wh = p_Wkvh; ga.bias = p_bkv; ga.rsum = p_rskv;
        ga.Yh = p_bufB; ga.O = 2 * C_;
        gemm_lnh_kernel<<<dim3(2 * C_ / 128, HW_ / 128, B_), 256>>>(ga);
    }

    // 3. merged q+k dwconvs (register-strip, 4-row patches) -> g_q, g_k (+sumsq)
    dwqk_kernel<<<dim3(2, 2 * C_, B_), 256>>>(q_dw_w, q_dw_b, kv_dw_w, kv_dw_b);

    // 4. v dwconv + positional branch -> g_v, g_pe
    vpe_kernel<<<dim3(8, C_, B_), 256>>>(kv_dw_w, kv_dw_b, pe1_w, pe2_w);

    // 5. gram (bf16 mma, split-K=4), softmax with fused norms
    gram_mma<<<dim3(GSEG, HEADS_, B_), 256>>>();
    softmax_kernel<<<B_ * HEADS_, 32>>>(temperature);

    // 6. fold attn into output projection; final fused GEMM
    buildM_kernel<<<dim3(HEADS_, B_), 256>>>(ao_w);
    gemm_outh_kernel<<<dim3(C_ / 128, HW_ / 128, B_), 256>>>(ao_b, hx, out);
}